// round 14
// baseline (speedup 1.0000x reference)
#include <cuda_runtime.h>
#include <math.h>
#include <stdint.h>

// ---------------- constants ----------------
#define K2        72.13475204444817f     // (1/EPS)*log2(e)
#define TWOK2     144.26950408889634f    // 2*K2
#define EPS_LN2   0.013862943611198906f  // EPS*ln(2) == 1/K2
#define EPSLOG1024 0.13862943611198905f
#define EPSLOG4096 0.16635532333438687f
#define IDENT_MASK 0x7FFFFFFF
typedef unsigned long long ull;

// ---------------- scratch ----------------
__device__ float g_gtfps[2 * 1024 * 3];
__device__ float g_f1[2 * 1024];
__device__ float g_g1[2 * 1024];
__device__ float g_f2[2 * 4096];
__device__ float g_g2[2 * 4096];
__device__ float g_emd1r[2 * 1024];
__device__ float g_emd2r[2 * 4096];
__device__ float g_d1c[2 * 4096];
__device__ float g_d2c[2 * 512];
__device__ float g_d1f[2 * 4096];
__device__ float g_d2f[2 * 4096];

// ---------------- fast math helpers ----------------
__device__ __forceinline__ float ex2(float x) {
    float y; asm("ex2.approx.ftz.f32 %0, %1;" : "=f"(y) : "f"(x)); return y;
}
__device__ __forceinline__ float lg2(float x) {
    float y; asm("lg2.approx.f32 %0, %1;" : "=f"(y) : "f"(x)); return y;
}
__device__ __forceinline__ ull pack2(float a, float b) {
    ull r; asm("mov.b64 %0, {%1, %2};" : "=l"(r) : "f"(a), "f"(b)); return r;
}
__device__ __forceinline__ void unpack2(ull v, float& a, float& b) {
    asm("mov.b64 {%0, %1}, %2;" : "=f"(a), "=f"(b) : "l"(v));
}
__device__ __forceinline__ ull fma2(ull a, ull b, ull c) {
    ull d; asm("fma.rn.f32x2 %0, %1, %2, %3;" : "=l"(d) : "l"(a), "l"(b), "l"(c)); return d;
}
__device__ __forceinline__ ull add2(ull a, ull b) {
    ull d; asm("add.rn.f32x2 %0, %1, %2;" : "=l"(d) : "l"(a), "l"(b)); return d;
}
__device__ __forceinline__ void lds2u64(unsigned addr, ull& a, ull& b) {
    asm volatile("ld.shared.v2.u64 {%0, %1}, [%2];" : "=l"(a), "=l"(b) : "r"(addr));
}
// predicated stores (no BSSY/BSYNC — ptxas won't emit this from C++ if{})
__device__ __forceinline__ void sts128_pred(int pred, unsigned addr,
                                            float a, float b, float c, float d) {
    asm volatile("{\n\t.reg .pred p;\n\tsetp.ne.u32 p, %0, 0;\n\t"
                 "@p st.shared.v4.f32 [%1], {%2, %3, %4, %5};\n\t}"
                 :: "r"(pred), "r"(addr), "f"(a), "f"(b), "f"(c), "f"(d));
}
__device__ __forceinline__ void stg_pred(int pred, float* p0, float a) {
    asm volatile("{\n\t.reg .pred p;\n\tsetp.ne.u32 p, %0, 0;\n\t"
                 "@p st.global.f32 [%1], %2;\n\t}"
                 :: "r"(pred), "l"(p0), "f"(a));
}

// ---------------- FPS: 256 threads, branch-light tail, coords in candidates ----
#define FPS_T 256
__global__ __launch_bounds__(FPS_T) void fps_kernel(const float* __restrict__ gt) {
    extern __shared__ float sh[];
    float* SX = sh;
    float* SY = sh + 4096;
    float* SZ = sh + 8192;
    __shared__ float4 scand[2][8];       // parity-dbl-buffered {val, x, y, z}

    int b = blockIdx.x;
    const float* P = gt + b * 4096 * 3;
    float* outp = g_gtfps + b * 1024 * 3;
    int t = threadIdx.x, lane = t & 31, wid = t >> 5;

    const float4* P4 = (const float4*)P;
    for (int k = t; k < 3072; k += FPS_T) {
        float4 v = P4[k];
        int e = 4 * k;
        float c[4] = {v.x, v.y, v.z, v.w};
#pragma unroll
        for (int q = 0; q < 4; q++) {
            int ei = e + q;
            sh[(ei % 3) * 4096 + (ei / 3)] = c[q];
        }
    }
    __syncthreads();

    int base = t * 16;                   // contiguous ownership -> exact tiebreak
    ull qx[8], qy[8], qz[8], qw[8];
    float dm[16];
#pragma unroll
    for (int j = 0; j < 8; j++) {
        float x0 = SX[base + 2 * j], x1 = SX[base + 2 * j + 1];
        float y0 = SY[base + 2 * j], y1 = SY[base + 2 * j + 1];
        float z0 = SZ[base + 2 * j], z1 = SZ[base + 2 * j + 1];
        qx[j] = pack2(x0, x1); qy[j] = pack2(y0, y1); qz[j] = pack2(z0, z1);
        qw[j] = pack2(fmaf(z0, z0, fmaf(y0, y0, x0 * x0)),
                      fmaf(z1, z1, fmaf(y1, y1, x1 * x1)));
        dm[2 * j] = 1e10f; dm[2 * j + 1] = 1e10f;
    }

    float lx = SX[0], ly = SY[0], lz = SZ[0];
    if (t == 0) { outp[0] = lx; outp[1] = ly; outp[2] = lz; }

    unsigned candAddr0 = (unsigned)__cvta_generic_to_shared(&scand[0][0]);

    for (int step = 1; step < 1024; step++) {
        int par = step & 1;
        float ll = fmaf(lz, lz, fmaf(ly, ly, lx * lx));
        ull nx = pack2(-2.0f * lx, -2.0f * lx);
        ull ny = pack2(-2.0f * ly, -2.0f * ly);
        ull nz = pack2(-2.0f * lz, -2.0f * lz);
        ull l2 = pack2(ll, ll);
        float mv = -1e30f;
#pragma unroll
        for (int j = 0; j < 8; j++) {
            ull d = fma2(qx[j], nx, qw[j]);
            d = fma2(qy[j], ny, d);
            d = fma2(qz[j], nz, d);
            d = add2(d, l2);
            float d0, d1; unpack2(d, d0, d1);
            dm[2 * j]     = fminf(dm[2 * j], d0);
            dm[2 * j + 1] = fminf(dm[2 * j + 1], d1);
            mv = fmaxf(mv, fmaxf(dm[2 * j], dm[2 * j + 1]));
        }
        // warp winner value (warp max positive -> int-bit compare exact)
        int mb = __float_as_int(mv);
        int M = __reduce_max_sync(0xffffffffu, mb);
        unsigned mk = __ballot_sync(0xffffffffu, mb == M);
        int src = __ffs(mk) - 1;                        // lowest lane = lowest idx
        int myidx = 0;
        if (lane == src) {                              // small divergent scan
            float Mf = __int_as_float(M);
            myidx = 0x7FFFFFFF;
#pragma unroll
            for (int j = 15; j >= 0; j--)
                if (dm[j] == Mf) myidx = base + j;      // downward -> lowest idx
        }
        int widx = __shfl_sync(0xffffffffu, myidx, src);
        // all lanes: broadcast LDS of warp-winner coords (uniform addr, free)
        float cx = SX[widx], cy = SY[widx], cz = SZ[widx];
        // lane 0 stores candidate {val, x, y, z} (predicated, no branch)
        sts128_pred(lane == 0, candAddr0 + (unsigned)(par * 128 + wid * 16),
                    __int_as_float(M), cx, cy, cz);
        __syncthreads();                                // the ONLY barrier
        // branchless merge of 8 candidates; strict > keeps lowest warp (=lowest idx)
        float4 c0 = scand[par][0], c1 = scand[par][1];
        float4 c2 = scand[par][2], c3 = scand[par][3];
        float4 c4 = scand[par][4], c5 = scand[par][5];
        float4 c6 = scand[par][6], c7 = scand[par][7];
#define SEL4(A, B) { bool bg = (B).x > (A).x; \
        (A).x = bg ? (B).x : (A).x; (A).y = bg ? (B).y : (A).y; \
        (A).z = bg ? (B).z : (A).z; (A).w = bg ? (B).w : (A).w; }
        SEL4(c0, c1); SEL4(c2, c3); SEL4(c4, c5); SEL4(c6, c7);
        SEL4(c0, c2); SEL4(c4, c6);
        SEL4(c0, c4);
#undef SEL4
        lx = c0.y; ly = c0.z; lz = c0.w;
        // t==0 output store (predicated, off critical path, no branch)
        stg_pred(t == 0, outp + step * 3 + 0, lx);
        stg_pred(t == 0, outp + step * 3 + 1, ly);
        stg_pred(t == 0, outp + step * 3 + 2, lz);
    }
}

// ---------------- pairwise kernel: 4 rows x 2-warp j-split, split A/B layout ----------------
// A region (8*Nq bytes): per pair p, 16B {x0,x1,y0,y1}; B region: {z0,z1,w0,w1}.
// MODE 0/1: xyz*TWOK2, w = K2*g - K2*|q|^2; MODE 2: raw coords, w=|q|^2.
// Warp w: row-group g=w>>1 (4 rows), j-half h=w&1; exact partial LSE, merged after 1 barrier.
template <int MODE, int NTT>
__global__ __launch_bounds__(NTT) void pair_kernel(
    const float* __restrict__ Pbase, int Np, int maskP, int strideP,
    const float* __restrict__ Qbase, int Nq, int maskQ, int strideQ,
    const float* __restrict__ vinBase, float* __restrict__ voutBase,
    float epsLogN, const int* __restrict__ itersPtr, int myIter)
{
    constexpr int ROWS = NTT / 16;
    if (itersPtr && myIter >= *itersPtr) return;
    int b = blockIdx.y;
    const float* P = Pbase + b * strideP;
    const float* Q = Qbase + b * strideQ;
    const float* vin = vinBase ? (vinBase + b * Nq) : nullptr;

    extern __shared__ float sh[];
    float* shB = sh + 2 * Nq;
    float* shG = sh + 4 * Nq;
    __shared__ float s_pa[28][4];
    __shared__ float s_pb[28][4];
    __shared__ float s_pc[28][4];

    for (int j = threadIdx.x; j < Nq; j += NTT) {
        int qj = j & maskQ;
        float qx = Q[qj * 3], qy = Q[qj * 3 + 1], qz = Q[qj * 3 + 2];
        float qw = fmaf(qz, qz, fmaf(qy, qy, qx * qx));
        int p = j >> 1, h2 = j & 1;
        if (MODE == 2) {
            sh[4 * p + h2]      = qx;
            sh[4 * p + 2 + h2]  = qy;
            shB[4 * p + h2]     = qz;
            shB[4 * p + 2 + h2] = qw;
        } else {
            float gv = vin ? vin[j] : 0.0f;
            sh[4 * p + h2]      = qx * TWOK2;
            sh[4 * p + 2 + h2]  = qy * TWOK2;
            shB[4 * p + h2]     = qz * TWOK2;
            shB[4 * p + 2 + h2] = fmaf(-K2, qw, gv * K2);
            if (MODE == 1) shG[j] = gv * K2;
        }
    }
    __syncthreads();

    int warp = threadIdx.x >> 5, lane = threadIdx.x & 31;
    int g = warp >> 1, h = warp & 1;
    int i0 = blockIdx.x * ROWS + g * 4;
    bool valid = i0 < Np;

    float px[4], py[4], pz[4], x2[4];
    unsigned sbase = (unsigned)__cvta_generic_to_shared(sh);
    unsigned aA0 = sbase + (unsigned)(h * 4 * Nq) + lane * 16;
    unsigned aB0 = aA0 + (unsigned)(8 * Nq);
    int iters = Nq >> 7;

    if (valid) {
#pragma unroll
        for (int r = 0; r < 4; r++) {
            int pi = (i0 + r) & maskP;
            px[r] = P[pi * 3]; py[r] = P[pi * 3 + 1]; pz[r] = P[pi * 3 + 2];
            x2[r] = fmaf(pz[r], pz[r], fmaf(py[r], py[r], px[r] * px[r]));
        }

        if (MODE == 2) {
            ull nx[4], ny[4], nz[4];
            float mn[4];
#pragma unroll
            for (int r = 0; r < 4; r++) {
                nx[r] = pack2(-2.0f * px[r], -2.0f * px[r]);
                ny[r] = pack2(-2.0f * py[r], -2.0f * py[r]);
                nz[r] = pack2(-2.0f * pz[r], -2.0f * pz[r]);
                mn[r] = 3.4e38f;
            }
            unsigned aA = aA0, aB = aB0;
#pragma unroll 4
            for (int k = 0; k < iters; k++, aA += 512, aB += 512) {
                ull x01, y01, z01, w01;
                lds2u64(aA, x01, y01);
                lds2u64(aB, z01, w01);
#pragma unroll
                for (int r = 0; r < 4; r++) {
                    ull acc = fma2(x01, nx[r], w01);
                    acc = fma2(y01, ny[r], acc);
                    acc = fma2(z01, nz[r], acc);
                    float t0, t1; unpack2(acc, t0, t1);
                    mn[r] = fminf(mn[r], fminf(t0, t1));
                }
            }
#pragma unroll
            for (int off = 16; off; off >>= 1)
#pragma unroll
                for (int r = 0; r < 4; r++)
                    mn[r] = fminf(mn[r], __shfl_xor_sync(0xffffffffu, mn[r], off));
            if (lane == 0)
#pragma unroll
                for (int r = 0; r < 4; r++) s_pa[warp][r] = mn[r];
        } else {
            ull vx[4], vy[4], vz[4];
#pragma unroll
            for (int r = 0; r < 4; r++) {
                vx[r] = pack2(px[r], px[r]);
                vy[r] = pack2(py[r], py[r]);
                vz[r] = pack2(pz[r], pz[r]);
            }
            float m[4];
#pragma unroll
            for (int r = 0; r < 4; r++) m[r] = -3.0e38f;
            {
                unsigned aA = aA0, aB = aB0;
#pragma unroll 4
                for (int k = 0; k < iters; k++, aA += 512, aB += 512) {
                    ull x01, y01, z01, w01;
                    lds2u64(aA, x01, y01);
                    lds2u64(aB, z01, w01);
#pragma unroll
                    for (int r = 0; r < 4; r++) {
                        ull acc = fma2(x01, vx[r], w01);
                        acc = fma2(y01, vy[r], acc);
                        acc = fma2(z01, vz[r], acc);
                        float t0, t1; unpack2(acc, t0, t1);
                        m[r] = fmaxf(m[r], fmaxf(t0, t1));
                    }
                }
#pragma unroll
                for (int off = 16; off; off >>= 1)
#pragma unroll
                    for (int r = 0; r < 4; r++)
                        m[r] = fmaxf(m[r], __shfl_xor_sync(0xffffffffu, m[r], off));
            }
            ull nm[4];
#pragma unroll
            for (int r = 0; r < 4; r++) nm[r] = pack2(-m[r], -m[r]);

            if (MODE == 0) {
                float s[4] = {0.0f, 0.0f, 0.0f, 0.0f};
                unsigned aA = aA0, aB = aB0;
#pragma unroll 4
                for (int k = 0; k < iters; k++, aA += 512, aB += 512) {
                    ull x01, y01, z01, w01;
                    lds2u64(aA, x01, y01);
                    lds2u64(aB, z01, w01);
#pragma unroll
                    for (int r = 0; r < 4; r++) {
                        ull acc = fma2(x01, vx[r], w01);
                        acc = fma2(y01, vy[r], acc);
                        acc = fma2(z01, vz[r], acc);
                        acc = add2(acc, nm[r]);
                        float t0, t1; unpack2(acc, t0, t1);
                        s[r] += ex2(t0) + ex2(t1);
                    }
                }
#pragma unroll
                for (int off = 16; off; off >>= 1)
#pragma unroll
                    for (int r = 0; r < 4; r++)
                        s[r] += __shfl_xor_sync(0xffffffffu, s[r], off);
                if (lane == 0)
#pragma unroll
                    for (int r = 0; r < 4; r++) {
                        s_pa[warp][r] = m[r];
                        s_pb[warp][r] = s[r];
                    }
            } else {
                float s[4] = {0.0f, 0.0f, 0.0f, 0.0f};
                float sc[4] = {0.0f, 0.0f, 0.0f, 0.0f};
                unsigned aA = aA0, aB = aB0;
                unsigned aG = sbase + 16u * (unsigned)Nq + (unsigned)(h * 2 * Nq) + lane * 8;
#pragma unroll 2
                for (int k = 0; k < iters; k++, aA += 512, aB += 512, aG += 256) {
                    ull x01, y01, z01, w01;
                    lds2u64(aA, x01, y01);
                    lds2u64(aB, z01, w01);
                    float2 gv;
                    asm volatile("ld.shared.v2.f32 {%0, %1}, [%2];"
                                 : "=f"(gv.x), "=f"(gv.y) : "r"(aG));
#pragma unroll
                    for (int r = 0; r < 4; r++) {
                        ull acc = fma2(x01, vx[r], w01);
                        acc = fma2(y01, vy[r], acc);
                        acc = fma2(z01, vz[r], acc);
                        acc = add2(acc, nm[r]);
                        float t0, t1; unpack2(acc, t0, t1);
                        float e0 = ex2(t0), e1 = ex2(t1);
                        float C0 = fmaf(gv.x - (t0 + m[r]), EPS_LN2, x2[r]);
                        float C1 = fmaf(gv.y - (t1 + m[r]), EPS_LN2, x2[r]);
                        s[r] += e0 + e1;
                        sc[r] = fmaf(e0, C0, sc[r]);
                        sc[r] = fmaf(e1, C1, sc[r]);
                    }
                }
#pragma unroll
                for (int off = 16; off; off >>= 1)
#pragma unroll
                    for (int r = 0; r < 4; r++) {
                        s[r]  += __shfl_xor_sync(0xffffffffu, s[r], off);
                        sc[r] += __shfl_xor_sync(0xffffffffu, sc[r], off);
                    }
                if (lane == 0)
#pragma unroll
                    for (int r = 0; r < 4; r++) {
                        s_pa[warp][r] = m[r];
                        s_pb[warp][r] = s[r];
                        s_pc[warp][r] = sc[r];
                    }
            }
        }
    }
    __syncthreads();

    if (valid && h == 0 && lane == 0) {
#pragma unroll
        for (int r = 0; r < 4; r++) {
            if (MODE == 2) {
                float mn = fminf(s_pa[warp][r], s_pa[warp + 1][r]);
                voutBase[b * Np + i0 + r] = fmaxf(mn + x2[r], 0.0f);
            } else {
                float m0 = s_pa[warp][r], m1 = s_pa[warp + 1][r];
                float s0 = s_pb[warp][r], s1 = s_pb[warp + 1][r];
                float M = fmaxf(m0, m1);
                float e0 = ex2(m0 - M), e1 = ex2(m1 - M);
                float s = fmaf(s0, e0, s1 * e1);
                if (MODE == 0) {
                    voutBase[b * Np + i0 + r] =
                        fmaf(-EPS_LN2, (M - K2 * x2[r]) + lg2(s), -epsLogN);
                } else {
                    float sc = fmaf(s_pc[warp][r], e0, s_pc[warp + 1][r] * e1);
                    voutBase[b * Np + i0 + r] = sqrtf(sc / s);
                }
            }
        }
    }
}

// ---------------- reductions / final scalar outputs ----------------
__device__ __forceinline__ float blk_sum(float v, float* shp) {
    int lane = threadIdx.x & 31, wid = threadIdx.x >> 5;
#pragma unroll
    for (int off = 16; off; off >>= 1) v += __shfl_xor_sync(0xffffffffu, v, off);
    if (lane == 0) shp[wid] = v;
    __syncthreads();
    float r = 0.0f;
    if (wid == 0) {
        r = shp[lane];
#pragma unroll
        for (int off = 16; off; off >>= 1) r += __shfl_xor_sync(0xffffffffu, r, off);
    }
    __syncthreads();
    return r;
}

__global__ __launch_bounds__(1024) void finalize_kernel(float* __restrict__ out) {
    __shared__ float shp[32];
    int b = blockIdx.x;
    int t = threadIdx.x;
    const int BASE = 27648;

    float v = g_emd1r[b * 1024 + t];
    v = blk_sum(v, shp);
    if (t == 0) out[BASE + 0 + b] = v * (1.0f / 1024.0f);

    v = 0.0f;
    for (int i = t; i < 4096; i += 1024) v += g_emd2r[b * 4096 + i];
    v = blk_sum(v, shp);
    if (t == 0) out[BASE + 2 + b] = v * (1.0f / 4096.0f);

    float vs = 0.0f, vt = 0.0f;
    for (int i = t; i < 4096; i += 1024) { float d = g_d1c[b * 4096 + i]; vs += sqrtf(d); vt += d; }
    vs = blk_sum(vs, shp); vt = blk_sum(vt, shp);
    float vs2 = 0.0f, vt2 = 0.0f;
    if (t < 512) { float d = g_d2c[b * 512 + t]; vs2 = sqrtf(d); vt2 = d; }
    vs2 = blk_sum(vs2, shp); vt2 = blk_sum(vt2, shp);
    if (t == 0) {
        out[BASE + 4 + b] = (vs * (1.0f / 4096.0f) + vs2 * (1.0f / 512.0f)) * 0.5f;
        out[BASE + 8 + b] = vt * (1.0f / 4096.0f) + vt2 * (1.0f / 512.0f);
    }

    vs = 0.0f; vt = 0.0f;
    for (int i = t; i < 4096; i += 1024) { float d = g_d1f[b * 4096 + i]; vs += sqrtf(d); vt += d; }
    vs = blk_sum(vs, shp); vt = blk_sum(vt, shp);
    vs2 = 0.0f; vt2 = 0.0f;
    for (int i = t; i < 4096; i += 1024) { float d = g_d2f[b * 4096 + i]; vs2 += sqrtf(d); vt2 += d; }
    vs2 = blk_sum(vs2, shp); vt2 = blk_sum(vt2, shp);
    if (t == 0) {
        out[BASE + 6 + b]  = (vs + vs2) * (1.0f / 4096.0f) * 0.5f;
        out[BASE + 10 + b] = (vt + vt2) * (1.0f / 4096.0f);
    }
}

// ---------------- launch ----------------
extern "C" void kernel_launch(void* const* d_in, const int* in_sizes, int n_in,
                              void* d_out, int out_size) {
    const float* coarse = (const float*)d_in[0];
    const float* fine   = (const float*)d_in[1];
    const float* gt     = (const float*)d_in[2];
    const int*   iters  = (const int*)d_in[3];
    float* out = (float*)d_out;

    static cudaStream_t s1 = nullptr;
    static cudaEvent_t evFork = nullptr, evJoin = nullptr;
    if (!s1) {
        cudaStreamCreateWithFlags(&s1, cudaStreamNonBlocking);
        cudaEventCreateWithFlags(&evFork, cudaEventDisableTiming);
        cudaEventCreateWithFlags(&evJoin, cudaEventDisableTiming);
        cudaFuncSetAttribute((const void*)pair_kernel<0,896>, cudaFuncAttributeMaxDynamicSharedMemorySize, 84000);
        cudaFuncSetAttribute((const void*)pair_kernel<1,896>, cudaFuncAttributeMaxDynamicSharedMemorySize, 84000);
        cudaFuncSetAttribute((const void*)pair_kernel<2,896>, cudaFuncAttributeMaxDynamicSharedMemorySize, 84000);
        cudaFuncSetAttribute((const void*)pair_kernel<0,256>, cudaFuncAttributeMaxDynamicSharedMemorySize, 84000);
        cudaFuncSetAttribute((const void*)pair_kernel<1,256>, cudaFuncAttributeMaxDynamicSharedMemorySize, 84000);
        cudaFuncSetAttribute((const void*)pair_kernel<2,256>, cudaFuncAttributeMaxDynamicSharedMemorySize, 84000);
        cudaFuncSetAttribute((const void*)fps_kernel, cudaFuncAttributeMaxDynamicSharedMemorySize, 49400);
    }

    float *gtfps, *f1, *g1, *f2, *g2, *e1r, *e2r, *d1c, *d2c, *d1f, *d2f;
    cudaGetSymbolAddress((void**)&gtfps, g_gtfps);
    cudaGetSymbolAddress((void**)&f1, g_f1);
    cudaGetSymbolAddress((void**)&g1, g_g1);
    cudaGetSymbolAddress((void**)&f2, g_f2);
    cudaGetSymbolAddress((void**)&g2, g_g2);
    cudaGetSymbolAddress((void**)&e1r, g_emd1r);
    cudaGetSymbolAddress((void**)&e2r, g_emd2r);
    cudaGetSymbolAddress((void**)&d1c, g_d1c);
    cudaGetSymbolAddress((void**)&d2c, g_d2c);
    cudaGetSymbolAddress((void**)&d1f, g_d1f);
    cudaGetSymbolAddress((void**)&d2f, g_d2f);

    // ---- fork: FPS + EMD1 on s1 ----
    cudaEventRecord(evFork, 0);
    cudaStreamWaitEvent(s1, evFork, 0);
    fps_kernel<<<2, FPS_T, 49400, s1>>>(gt);

    cudaMemcpyAsync(out,        coarse, 2 * 512 * 3 * sizeof(float),  cudaMemcpyDeviceToDevice);
    cudaMemcpyAsync(out + 3072, fine,   2 * 4096 * 3 * sizeof(float), cudaMemcpyDeviceToDevice);

    const int GX4 = (4096 + 55) / 56;   // 74 -> grid (74,2) = 148 = 1 block/SM
    const int GX1 = 1024 / 16;          // 64 (NTT=256, 16 rows/block)
    const int GXC = 512 / 16;           // 32

    // ---- stream 0: EMD2 chain ----
    for (int it = 0; it < 4; it++) {
        pair_kernel<0,896><<<dim3(GX4, 2), 896, 4096 * 16>>>(
            fine, 4096, IDENT_MASK, 4096 * 3, gt, 4096, IDENT_MASK, 4096 * 3,
            it == 0 ? nullptr : g2, f2, EPSLOG4096, iters, it);
        pair_kernel<0,896><<<dim3(GX4, 2), 896, 4096 * 16>>>(
            gt, 4096, IDENT_MASK, 4096 * 3, fine, 4096, IDENT_MASK, 4096 * 3,
            f2, g2, EPSLOG4096, iters, it);
    }
    pair_kernel<1,896><<<dim3(GX4, 2), 896, 4096 * 20>>>(
        fine, 4096, IDENT_MASK, 4096 * 3, gt, 4096, IDENT_MASK, 4096 * 3,
        g2, e2r, 0.0f, nullptr, 0);

    // ---- stream 0: chamfers ----
    pair_kernel<2,896><<<dim3(GX4, 2), 896, 4096 * 16>>>(
        fine, 4096, IDENT_MASK, 4096 * 3, gt, 4096, IDENT_MASK, 4096 * 3,
        nullptr, d2f, 0.0f, nullptr, 0);
    pair_kernel<2,896><<<dim3(GX4, 2), 896, 4096 * 16>>>(
        gt, 4096, IDENT_MASK, 4096 * 3, fine, 4096, IDENT_MASK, 4096 * 3,
        nullptr, d1f, 0.0f, nullptr, 0);
    pair_kernel<2,896><<<dim3(GX4, 2), 896, 512 * 16>>>(
        gt, 4096, IDENT_MASK, 4096 * 3, coarse, 512, IDENT_MASK, 512 * 3,
        nullptr, d1c, 0.0f, nullptr, 0);
    pair_kernel<2,256><<<dim3(GXC, 2), 256, 4096 * 16>>>(
        coarse, 512, IDENT_MASK, 512 * 3, gt, 4096, IDENT_MASK, 4096 * 3,
        nullptr, d2c, 0.0f, nullptr, 0);

    // ---- s1: EMD1 chain (after FPS; NTT=256 -> 128 blocks) ----
    for (int it = 0; it < 4; it++) {
        pair_kernel<0,256><<<dim3(GX1, 2), 256, 1024 * 16, s1>>>(
            coarse, 1024, 511, 512 * 3, gtfps, 1024, IDENT_MASK, 1024 * 3,
            it == 0 ? nullptr : g1, f1, EPSLOG1024, iters, it);
        pair_kernel<0,256><<<dim3(GX1, 2), 256, 1024 * 16, s1>>>(
            gtfps, 1024, IDENT_MASK, 1024 * 3, coarse, 1024, 511, 512 * 3,
            f1, g1, EPSLOG1024, iters, it);
    }
    pair_kernel<1,256><<<dim3(GX1, 2), 256, 1024 * 20, s1>>>(
        coarse, 1024, 511, 512 * 3, gtfps, 1024, IDENT_MASK, 1024 * 3,
        g1, e1r, 0.0f, nullptr, 0);

    // ---- join, finalize ----
    cudaEventRecord(evJoin, s1);
    cudaStreamWaitEvent(0, evJoin, 0);
    finalize_kernel<<<2, 1024>>>(out);
}

// round 15
// speedup vs baseline: 1.0020x; 1.0020x over previous
#include <cuda_runtime.h>
#include <math.h>
#include <stdint.h>

// ---------------- constants ----------------
#define K2        72.13475204444817f     // (1/EPS)*log2(e)
#define TWOK2     144.26950408889634f    // 2*K2
#define EPS_LN2   0.013862943611198906f  // EPS*ln(2) == 1/K2
#define EPSLOG1024 0.13862943611198905f
#define EPSLOG4096 0.16635532333438687f
#define IDENT_MASK 0x7FFFFFFF
#define SMEM_BIG  190000                 // exclusion request: blocks FPS-SM co-residency
typedef unsigned long long ull;

// ---------------- scratch ----------------
__device__ float g_gtfps[2 * 1024 * 3];
__device__ float g_f1[2 * 1024];
__device__ float g_g1[2 * 1024];
__device__ float g_f2[2 * 4096];
__device__ float g_g2[2 * 4096];
__device__ float g_emd1r[2 * 1024];
__device__ float g_emd2r[2 * 4096];
__device__ float g_d1c[2 * 4096];
__device__ float g_d2c[2 * 512];
__device__ float g_d1f[2 * 4096];
__device__ float g_d2f[2 * 4096];

// ---------------- fast math helpers ----------------
__device__ __forceinline__ float ex2(float x) {
    float y; asm("ex2.approx.ftz.f32 %0, %1;" : "=f"(y) : "f"(x)); return y;
}
__device__ __forceinline__ float lg2(float x) {
    float y; asm("lg2.approx.f32 %0, %1;" : "=f"(y) : "f"(x)); return y;
}
__device__ __forceinline__ ull pack2(float a, float b) {
    ull r; asm("mov.b64 %0, {%1, %2};" : "=l"(r) : "f"(a), "f"(b)); return r;
}
__device__ __forceinline__ void unpack2(ull v, float& a, float& b) {
    asm("mov.b64 {%0, %1}, %2;" : "=f"(a), "=f"(b) : "l"(v));
}
__device__ __forceinline__ ull fma2(ull a, ull b, ull c) {
    ull d; asm("fma.rn.f32x2 %0, %1, %2, %3;" : "=l"(d) : "l"(a), "l"(b), "l"(c)); return d;
}
__device__ __forceinline__ ull add2(ull a, ull b) {
    ull d; asm("add.rn.f32x2 %0, %1, %2;" : "=l"(d) : "l"(a), "l"(b)); return d;
}
__device__ __forceinline__ void lds2u64(unsigned addr, ull& a, ull& b) {
    asm volatile("ld.shared.v2.u64 {%0, %1}, [%2];" : "=l"(a), "=l"(b) : "r"(addr));
}
__device__ __forceinline__ void sts128_pred(int pred, unsigned addr,
                                            float a, float b, float c, float d) {
    asm volatile("{\n\t.reg .pred p;\n\tsetp.ne.u32 p, %0, 0;\n\t"
                 "@p st.shared.v4.f32 [%1], {%2, %3, %4, %5};\n\t}"
                 :: "r"(pred), "r"(addr), "f"(a), "f"(b), "f"(c), "f"(d));
}
__device__ __forceinline__ void stg_pred(int pred, float* p0, float a) {
    asm volatile("{\n\t.reg .pred p;\n\tsetp.ne.u32 p, %0, 0;\n\t"
                 "@p st.global.f32 [%1], %2;\n\t}"
                 :: "r"(pred), "l"(p0), "f"(a));
}

// ---------------- FPS: 256 threads, branch-light tail, coords in candidates ----
#define FPS_T 256
__global__ __launch_bounds__(FPS_T) void fps_kernel(const float* __restrict__ gt) {
    extern __shared__ float sh[];
    float* SX = sh;
    float* SY = sh + 4096;
    float* SZ = sh + 8192;
    __shared__ float4 scand[2][8];       // parity-dbl-buffered {val, x, y, z}

    int b = blockIdx.x;
    const float* P = gt + b * 4096 * 3;
    float* outp = g_gtfps + b * 1024 * 3;
    int t = threadIdx.x, lane = t & 31, wid = t >> 5;

    const float4* P4 = (const float4*)P;
    for (int k = t; k < 3072; k += FPS_T) {
        float4 v = P4[k];
        int e = 4 * k;
        float c[4] = {v.x, v.y, v.z, v.w};
#pragma unroll
        for (int q = 0; q < 4; q++) {
            int ei = e + q;
            sh[(ei % 3) * 4096 + (ei / 3)] = c[q];
        }
    }
    __syncthreads();

    int base = t * 16;                   // contiguous ownership -> exact tiebreak
    ull qx[8], qy[8], qz[8], qw[8];
    float dm[16];
#pragma unroll
    for (int j = 0; j < 8; j++) {
        float x0 = SX[base + 2 * j], x1 = SX[base + 2 * j + 1];
        float y0 = SY[base + 2 * j], y1 = SY[base + 2 * j + 1];
        float z0 = SZ[base + 2 * j], z1 = SZ[base + 2 * j + 1];
        qx[j] = pack2(x0, x1); qy[j] = pack2(y0, y1); qz[j] = pack2(z0, z1);
        qw[j] = pack2(fmaf(z0, z0, fmaf(y0, y0, x0 * x0)),
                      fmaf(z1, z1, fmaf(y1, y1, x1 * x1)));
        dm[2 * j] = 1e10f; dm[2 * j + 1] = 1e10f;
    }

    float lx = SX[0], ly = SY[0], lz = SZ[0];
    if (t == 0) { outp[0] = lx; outp[1] = ly; outp[2] = lz; }

    unsigned candAddr0 = (unsigned)__cvta_generic_to_shared(&scand[0][0]);

    for (int step = 1; step < 1024; step++) {
        int par = step & 1;
        float ll = fmaf(lz, lz, fmaf(ly, ly, lx * lx));
        ull nx = pack2(-2.0f * lx, -2.0f * lx);
        ull ny = pack2(-2.0f * ly, -2.0f * ly);
        ull nz = pack2(-2.0f * lz, -2.0f * lz);
        ull l2 = pack2(ll, ll);
        float mv = -1e30f;
#pragma unroll
        for (int j = 0; j < 8; j++) {
            ull d = fma2(qx[j], nx, qw[j]);
            d = fma2(qy[j], ny, d);
            d = fma2(qz[j], nz, d);
            d = add2(d, l2);
            float d0, d1; unpack2(d, d0, d1);
            dm[2 * j]     = fminf(dm[2 * j], d0);
            dm[2 * j + 1] = fminf(dm[2 * j + 1], d1);
            mv = fmaxf(mv, fmaxf(dm[2 * j], dm[2 * j + 1]));
        }
        int mb = __float_as_int(mv);
        int M = __reduce_max_sync(0xffffffffu, mb);
        unsigned mk = __ballot_sync(0xffffffffu, mb == M);
        int src = __ffs(mk) - 1;                        // lowest lane = lowest idx
        int myidx = 0;
        if (lane == src) {
            float Mf = __int_as_float(M);
            myidx = 0x7FFFFFFF;
#pragma unroll
            for (int j = 15; j >= 0; j--)
                if (dm[j] == Mf) myidx = base + j;      // downward -> lowest idx
        }
        int widx = __shfl_sync(0xffffffffu, myidx, src);
        float cx = SX[widx], cy = SY[widx], cz = SZ[widx];
        sts128_pred(lane == 0, candAddr0 + (unsigned)(par * 128 + wid * 16),
                    __int_as_float(M), cx, cy, cz);
        __syncthreads();
        float4 c0 = scand[par][0], c1 = scand[par][1];
        float4 c2 = scand[par][2], c3 = scand[par][3];
        float4 c4 = scand[par][4], c5 = scand[par][5];
        float4 c6 = scand[par][6], c7 = scand[par][7];
#define SEL4(A, B) { bool bg = (B).x > (A).x; \
        (A).x = bg ? (B).x : (A).x; (A).y = bg ? (B).y : (A).y; \
        (A).z = bg ? (B).z : (A).z; (A).w = bg ? (B).w : (A).w; }
        SEL4(c0, c1); SEL4(c2, c3); SEL4(c4, c5); SEL4(c6, c7);
        SEL4(c0, c2); SEL4(c4, c6);
        SEL4(c0, c4);
#undef SEL4
        lx = c0.y; ly = c0.z; lz = c0.w;
        stg_pred(t == 0, outp + step * 3 + 0, lx);
        stg_pred(t == 0, outp + step * 3 + 1, ly);
        stg_pred(t == 0, outp + step * 3 + 2, lz);
    }
}

// ---------------- pairwise kernel: 4 rows x 2-warp j-split, split A/B layout ----------------
template <int MODE, int NTT>
__global__ __launch_bounds__(NTT) void pair_kernel(
    const float* __restrict__ Pbase, int Np, int maskP, int strideP,
    const float* __restrict__ Qbase, int Nq, int maskQ, int strideQ,
    const float* __restrict__ vinBase, float* __restrict__ voutBase,
    float epsLogN, const int* __restrict__ itersPtr, int myIter)
{
    constexpr int ROWS = NTT / 16;
    constexpr int NW = NTT / 32;
    if (itersPtr && myIter >= *itersPtr) return;
    int b = blockIdx.y;
    const float* P = Pbase + b * strideP;
    const float* Q = Qbase + b * strideQ;
    const float* vin = vinBase ? (vinBase + b * Nq) : nullptr;

    extern __shared__ float sh[];
    float* shB = sh + 2 * Nq;
    float* shG = sh + 4 * Nq;
    __shared__ float s_pa[NW][4];
    __shared__ float s_pb[NW][4];
    __shared__ float s_pc[NW][4];

    for (int j = threadIdx.x; j < Nq; j += NTT) {
        int qj = j & maskQ;
        float qx = Q[qj * 3], qy = Q[qj * 3 + 1], qz = Q[qj * 3 + 2];
        float qw = fmaf(qz, qz, fmaf(qy, qy, qx * qx));
        int p = j >> 1, h2 = j & 1;
        if (MODE == 2) {
            sh[4 * p + h2]      = qx;
            sh[4 * p + 2 + h2]  = qy;
            shB[4 * p + h2]     = qz;
            shB[4 * p + 2 + h2] = qw;
        } else {
            float gv = vin ? vin[j] : 0.0f;
            sh[4 * p + h2]      = qx * TWOK2;
            sh[4 * p + 2 + h2]  = qy * TWOK2;
            shB[4 * p + h2]     = qz * TWOK2;
            shB[4 * p + 2 + h2] = fmaf(-K2, qw, gv * K2);
            if (MODE == 1) shG[j] = gv * K2;
        }
    }
    __syncthreads();

    int warp = threadIdx.x >> 5, lane = threadIdx.x & 31;
    int g = warp >> 1, h = warp & 1;
    int i0 = blockIdx.x * ROWS + g * 4;
    bool valid = i0 < Np;

    float px[4], py[4], pz[4], x2[4];
    unsigned sbase = (unsigned)__cvta_generic_to_shared(sh);
    unsigned aA0 = sbase + (unsigned)(h * 4 * Nq) + lane * 16;
    unsigned aB0 = aA0 + (unsigned)(8 * Nq);
    int iters = Nq >> 7;

    if (valid) {
#pragma unroll
        for (int r = 0; r < 4; r++) {
            int pi = (i0 + r) & maskP;
            px[r] = P[pi * 3]; py[r] = P[pi * 3 + 1]; pz[r] = P[pi * 3 + 2];
            x2[r] = fmaf(pz[r], pz[r], fmaf(py[r], py[r], px[r] * px[r]));
        }

        if (MODE == 2) {
            ull nx[4], ny[4], nz[4];
            float mn[4];
#pragma unroll
            for (int r = 0; r < 4; r++) {
                nx[r] = pack2(-2.0f * px[r], -2.0f * px[r]);
                ny[r] = pack2(-2.0f * py[r], -2.0f * py[r]);
                nz[r] = pack2(-2.0f * pz[r], -2.0f * pz[r]);
                mn[r] = 3.4e38f;
            }
            unsigned aA = aA0, aB = aB0;
#pragma unroll 4
            for (int k = 0; k < iters; k++, aA += 512, aB += 512) {
                ull x01, y01, z01, w01;
                lds2u64(aA, x01, y01);
                lds2u64(aB, z01, w01);
#pragma unroll
                for (int r = 0; r < 4; r++) {
                    ull acc = fma2(x01, nx[r], w01);
                    acc = fma2(y01, ny[r], acc);
                    acc = fma2(z01, nz[r], acc);
                    float t0, t1; unpack2(acc, t0, t1);
                    mn[r] = fminf(mn[r], fminf(t0, t1));
                }
            }
#pragma unroll
            for (int off = 16; off; off >>= 1)
#pragma unroll
                for (int r = 0; r < 4; r++)
                    mn[r] = fminf(mn[r], __shfl_xor_sync(0xffffffffu, mn[r], off));
            if (lane == 0)
#pragma unroll
                for (int r = 0; r < 4; r++) s_pa[warp][r] = mn[r];
        } else {
            ull vx[4], vy[4], vz[4];
#pragma unroll
            for (int r = 0; r < 4; r++) {
                vx[r] = pack2(px[r], px[r]);
                vy[r] = pack2(py[r], py[r]);
                vz[r] = pack2(pz[r], pz[r]);
            }
            float m[4];
#pragma unroll
            for (int r = 0; r < 4; r++) m[r] = -3.0e38f;
            {
                unsigned aA = aA0, aB = aB0;
#pragma unroll 4
                for (int k = 0; k < iters; k++, aA += 512, aB += 512) {
                    ull x01, y01, z01, w01;
                    lds2u64(aA, x01, y01);
                    lds2u64(aB, z01, w01);
#pragma unroll
                    for (int r = 0; r < 4; r++) {
                        ull acc = fma2(x01, vx[r], w01);
                        acc = fma2(y01, vy[r], acc);
                        acc = fma2(z01, vz[r], acc);
                        float t0, t1; unpack2(acc, t0, t1);
                        m[r] = fmaxf(m[r], fmaxf(t0, t1));
                    }
                }
#pragma unroll
                for (int off = 16; off; off >>= 1)
#pragma unroll
                    for (int r = 0; r < 4; r++)
                        m[r] = fmaxf(m[r], __shfl_xor_sync(0xffffffffu, m[r], off));
            }
            ull nm[4];
#pragma unroll
            for (int r = 0; r < 4; r++) nm[r] = pack2(-m[r], -m[r]);

            if (MODE == 0) {
                float s[4] = {0.0f, 0.0f, 0.0f, 0.0f};
                unsigned aA = aA0, aB = aB0;
#pragma unroll 4
                for (int k = 0; k < iters; k++, aA += 512, aB += 512) {
                    ull x01, y01, z01, w01;
                    lds2u64(aA, x01, y01);
                    lds2u64(aB, z01, w01);
#pragma unroll
                    for (int r = 0; r < 4; r++) {
                        ull acc = fma2(x01, vx[r], w01);
                        acc = fma2(y01, vy[r], acc);
                        acc = fma2(z01, vz[r], acc);
                        acc = add2(acc, nm[r]);
                        float t0, t1; unpack2(acc, t0, t1);
                        s[r] += ex2(t0) + ex2(t1);
                    }
                }
#pragma unroll
                for (int off = 16; off; off >>= 1)
#pragma unroll
                    for (int r = 0; r < 4; r++)
                        s[r] += __shfl_xor_sync(0xffffffffu, s[r], off);
                if (lane == 0)
#pragma unroll
                    for (int r = 0; r < 4; r++) {
                        s_pa[warp][r] = m[r];
                        s_pb[warp][r] = s[r];
                    }
            } else {
                float s[4] = {0.0f, 0.0f, 0.0f, 0.0f};
                float sc[4] = {0.0f, 0.0f, 0.0f, 0.0f};
                unsigned aA = aA0, aB = aB0;
                unsigned aG = sbase + 16u * (unsigned)Nq + (unsigned)(h * 2 * Nq) + lane * 8;
#pragma unroll 2
                for (int k = 0; k < iters; k++, aA += 512, aB += 512, aG += 256) {
                    ull x01, y01, z01, w01;
                    lds2u64(aA, x01, y01);
                    lds2u64(aB, z01, w01);
                    float2 gv;
                    asm volatile("ld.shared.v2.f32 {%0, %1}, [%2];"
                                 : "=f"(gv.x), "=f"(gv.y) : "r"(aG));
#pragma unroll
                    for (int r = 0; r < 4; r++) {
                        ull acc = fma2(x01, vx[r], w01);
                        acc = fma2(y01, vy[r], acc);
                        acc = fma2(z01, vz[r], acc);
                        acc = add2(acc, nm[r]);
                        float t0, t1; unpack2(acc, t0, t1);
                        float e0 = ex2(t0), e1 = ex2(t1);
                        float C0 = fmaf(gv.x - (t0 + m[r]), EPS_LN2, x2[r]);
                        float C1 = fmaf(gv.y - (t1 + m[r]), EPS_LN2, x2[r]);
                        s[r] += e0 + e1;
                        sc[r] = fmaf(e0, C0, sc[r]);
                        sc[r] = fmaf(e1, C1, sc[r]);
                    }
                }
#pragma unroll
                for (int off = 16; off; off >>= 1)
#pragma unroll
                    for (int r = 0; r < 4; r++) {
                        s[r]  += __shfl_xor_sync(0xffffffffu, s[r], off);
                        sc[r] += __shfl_xor_sync(0xffffffffu, sc[r], off);
                    }
                if (lane == 0)
#pragma unroll
                    for (int r = 0; r < 4; r++) {
                        s_pa[warp][r] = m[r];
                        s_pb[warp][r] = s[r];
                        s_pc[warp][r] = sc[r];
                    }
            }
        }
    }
    __syncthreads();

    if (valid && h == 0 && lane == 0) {
#pragma unroll
        for (int r = 0; r < 4; r++) {
            if (MODE == 2) {
                float mn = fminf(s_pa[warp][r], s_pa[warp + 1][r]);
                voutBase[b * Np + i0 + r] = fmaxf(mn + x2[r], 0.0f);
            } else {
                float m0 = s_pa[warp][r], m1 = s_pa[warp + 1][r];
                float s0 = s_pb[warp][r], s1 = s_pb[warp + 1][r];
                float M = fmaxf(m0, m1);
                float e0 = ex2(m0 - M), e1 = ex2(m1 - M);
                float s = fmaf(s0, e0, s1 * e1);
                if (MODE == 0) {
                    voutBase[b * Np + i0 + r] =
                        fmaf(-EPS_LN2, (M - K2 * x2[r]) + lg2(s), -epsLogN);
                } else {
                    float sc = fmaf(s_pc[warp][r], e0, s_pc[warp + 1][r] * e1);
                    voutBase[b * Np + i0 + r] = sqrtf(sc / s);
                }
            }
        }
    }
}

// ---------------- reductions / final scalar outputs ----------------
__device__ __forceinline__ float blk_sum(float v, float* shp) {
    int lane = threadIdx.x & 31, wid = threadIdx.x >> 5;
#pragma unroll
    for (int off = 16; off; off >>= 1) v += __shfl_xor_sync(0xffffffffu, v, off);
    if (lane == 0) shp[wid] = v;
    __syncthreads();
    float r = 0.0f;
    if (wid == 0) {
        r = shp[lane];
#pragma unroll
        for (int off = 16; off; off >>= 1) r += __shfl_xor_sync(0xffffffffu, r, off);
    }
    __syncthreads();
    return r;
}

__global__ __launch_bounds__(1024) void finalize_kernel(float* __restrict__ out) {
    __shared__ float shp[32];
    int b = blockIdx.x;
    int t = threadIdx.x;
    const int BASE = 27648;

    float v = g_emd1r[b * 1024 + t];
    v = blk_sum(v, shp);
    if (t == 0) out[BASE + 0 + b] = v * (1.0f / 1024.0f);

    v = 0.0f;
    for (int i = t; i < 4096; i += 1024) v += g_emd2r[b * 4096 + i];
    v = blk_sum(v, shp);
    if (t == 0) out[BASE + 2 + b] = v * (1.0f / 4096.0f);

    float vs = 0.0f, vt = 0.0f;
    for (int i = t; i < 4096; i += 1024) { float d = g_d1c[b * 4096 + i]; vs += sqrtf(d); vt += d; }
    vs = blk_sum(vs, shp); vt = blk_sum(vt, shp);
    float vs2 = 0.0f, vt2 = 0.0f;
    if (t < 512) { float d = g_d2c[b * 512 + t]; vs2 = sqrtf(d); vt2 = d; }
    vs2 = blk_sum(vs2, shp); vt2 = blk_sum(vt2, shp);
    if (t == 0) {
        out[BASE + 4 + b] = (vs * (1.0f / 4096.0f) + vs2 * (1.0f / 512.0f)) * 0.5f;
        out[BASE + 8 + b] = vt * (1.0f / 4096.0f) + vt2 * (1.0f / 512.0f);
    }

    vs = 0.0f; vt = 0.0f;
    for (int i = t; i < 4096; i += 1024) { float d = g_d1f[b * 4096 + i]; vs += sqrtf(d); vt += d; }
    vs = blk_sum(vs, shp); vt = blk_sum(vt, shp);
    vs2 = 0.0f; vt2 = 0.0f;
    for (int i = t; i < 4096; i += 1024) { float d = g_d2f[b * 4096 + i]; vs2 += sqrtf(d); vt2 += d; }
    vs2 = blk_sum(vs2, shp); vt2 = blk_sum(vt2, shp);
    if (t == 0) {
        out[BASE + 6 + b]  = (vs + vs2) * (1.0f / 4096.0f) * 0.5f;
        out[BASE + 10 + b] = (vt + vt2) * (1.0f / 4096.0f);
    }
}

// ---------------- launch ----------------
extern "C" void kernel_launch(void* const* d_in, const int* in_sizes, int n_in,
                              void* d_out, int out_size) {
    const float* coarse = (const float*)d_in[0];
    const float* fine   = (const float*)d_in[1];
    const float* gt     = (const float*)d_in[2];
    const int*   iters  = (const int*)d_in[3];
    float* out = (float*)d_out;

    static cudaStream_t s1 = nullptr;
    static cudaEvent_t evFork = nullptr, evJoin = nullptr;
    if (!s1) {
        cudaStreamCreateWithFlags(&s1, cudaStreamNonBlocking);
        cudaEventCreateWithFlags(&evFork, cudaEventDisableTiming);
        cudaEventCreateWithFlags(&evJoin, cudaEventDisableTiming);
        cudaFuncSetAttribute((const void*)pair_kernel<0,1024>, cudaFuncAttributeMaxDynamicSharedMemorySize, SMEM_BIG);
        cudaFuncSetAttribute((const void*)pair_kernel<1,1024>, cudaFuncAttributeMaxDynamicSharedMemorySize, SMEM_BIG);
        cudaFuncSetAttribute((const void*)pair_kernel<2,1024>, cudaFuncAttributeMaxDynamicSharedMemorySize, SMEM_BIG);
        cudaFuncSetAttribute((const void*)pair_kernel<0,256>, cudaFuncAttributeMaxDynamicSharedMemorySize, 84000);
        cudaFuncSetAttribute((const void*)pair_kernel<1,256>, cudaFuncAttributeMaxDynamicSharedMemorySize, 84000);
        cudaFuncSetAttribute((const void*)pair_kernel<2,256>, cudaFuncAttributeMaxDynamicSharedMemorySize, SMEM_BIG);
        cudaFuncSetAttribute((const void*)fps_kernel, cudaFuncAttributeMaxDynamicSharedMemorySize, 49400);
    }

    float *gtfps, *f1, *g1, *f2, *g2, *e1r, *e2r, *d1c, *d2c, *d1f, *d2f;
    cudaGetSymbolAddress((void**)&gtfps, g_gtfps);
    cudaGetSymbolAddress((void**)&f1, g_f1);
    cudaGetSymbolAddress((void**)&g1, g_g1);
    cudaGetSymbolAddress((void**)&f2, g_f2);
    cudaGetSymbolAddress((void**)&g2, g_g2);
    cudaGetSymbolAddress((void**)&e1r, g_emd1r);
    cudaGetSymbolAddress((void**)&e2r, g_emd2r);
    cudaGetSymbolAddress((void**)&d1c, g_d1c);
    cudaGetSymbolAddress((void**)&d2c, g_d2c);
    cudaGetSymbolAddress((void**)&d1f, g_d1f);
    cudaGetSymbolAddress((void**)&d2f, g_d2f);

    // ---- fork: FPS + EMD1 on s1 (FPS launched FIRST -> claims 2 SMs) ----
    cudaEventRecord(evFork, 0);
    cudaStreamWaitEvent(s1, evFork, 0);
    fps_kernel<<<2, FPS_T, 49400, s1>>>(gt);

    cudaMemcpyAsync(out,        coarse, 2 * 512 * 3 * sizeof(float),  cudaMemcpyDeviceToDevice);
    cudaMemcpyAsync(out + 3072, fine,   2 * 4096 * 3 * sizeof(float), cudaMemcpyDeviceToDevice);

    const int GX4 = 4096 / 64;          // 64 -> grid (64,2) = 128 blocks <= 146 free SMs
    const int GX1 = 1024 / 16;          // 64 (NTT=256)
    const int GXC = 512 / 16;           // 32

    // ---- stream 0: EMD2 chain (SMEM_BIG request = exclusive SM per block) ----
    for (int it = 0; it < 4; it++) {
        pair_kernel<0,1024><<<dim3(GX4, 2), 1024, SMEM_BIG>>>(
            fine, 4096, IDENT_MASK, 4096 * 3, gt, 4096, IDENT_MASK, 4096 * 3,
            it == 0 ? nullptr : g2, f2, EPSLOG4096, iters, it);
        pair_kernel<0,1024><<<dim3(GX4, 2), 1024, SMEM_BIG>>>(
            gt, 4096, IDENT_MASK, 4096 * 3, fine, 4096, IDENT_MASK, 4096 * 3,
            f2, g2, EPSLOG4096, iters, it);
    }
    pair_kernel<1,1024><<<dim3(GX4, 2), 1024, SMEM_BIG>>>(
        fine, 4096, IDENT_MASK, 4096 * 3, gt, 4096, IDENT_MASK, 4096 * 3,
        g2, e2r, 0.0f, nullptr, 0);

    // ---- stream 0: chamfers (also exclusive) ----
    pair_kernel<2,1024><<<dim3(GX4, 2), 1024, SMEM_BIG>>>(
        fine, 4096, IDENT_MASK, 4096 * 3, gt, 4096, IDENT_MASK, 4096 * 3,
        nullptr, d2f, 0.0f, nullptr, 0);
    pair_kernel<2,1024><<<dim3(GX4, 2), 1024, SMEM_BIG>>>(
        gt, 4096, IDENT_MASK, 4096 * 3, fine, 4096, IDENT_MASK, 4096 * 3,
        nullptr, d1f, 0.0f, nullptr, 0);
    pair_kernel<2,1024><<<dim3(GX4, 2), 1024, SMEM_BIG>>>(
        gt, 4096, IDENT_MASK, 4096 * 3, coarse, 512, IDENT_MASK, 512 * 3,
        nullptr, d1c, 0.0f, nullptr, 0);
    pair_kernel<2,256><<<dim3(GXC, 2), 256, SMEM_BIG>>>(
        coarse, 512, IDENT_MASK, 512 * 3, gt, 4096, IDENT_MASK, 4096 * 3,
        nullptr, d2c, 0.0f, nullptr, 0);

    // ---- s1: EMD1 chain (after FPS; stream0 drained by then) ----
    for (int it = 0; it < 4; it++) {
        pair_kernel<0,256><<<dim3(GX1, 2), 256, 1024 * 16, s1>>>(
            coarse, 1024, 511, 512 * 3, gtfps, 1024, IDENT_MASK, 1024 * 3,
            it == 0 ? nullptr : g1, f1, EPSLOG1024, iters, it);
        pair_kernel<0,256><<<dim3(GX1, 2), 256, 1024 * 16, s1>>>(
            gtfps, 1024, IDENT_MASK, 1024 * 3, coarse, 1024, 511, 512 * 3,
            f1, g1, EPSLOG1024, iters, it);
    }
    pair_kernel<1,256><<<dim3(GX1, 2), 256, 1024 * 20, s1>>>(
        coarse, 1024, 511, 512 * 3, gtfps, 1024, IDENT_MASK, 1024 * 3,
        g1, e1r, 0.0f, nullptr, 0);

    // ---- join, finalize ----
    cudaEventRecord(evJoin, s1);
    cudaStreamWaitEvent(0, evJoin, 0);
    finalize_kernel<<<2, 1024>>>(out);
}

// round 16
// speedup vs baseline: 1.1800x; 1.1776x over previous
#include <cuda_runtime.h>
#include <math.h>
#include <stdint.h>

// ---------------- constants ----------------
#define K2        72.13475204444817f     // (1/EPS)*log2(e)
#define TWOK2     144.26950408889634f    // 2*K2
#define EPS_LN2   0.013862943611198906f  // EPS*ln(2) == 1/K2
#define EPSLOG1024 0.13862943611198905f
#define EPSLOG4096 0.16635532333438687f
#define IDENT_MASK 0x7FFFFFFF
typedef unsigned long long ull;

// ---------------- scratch ----------------
__device__ float g_gtfps[2 * 1024 * 3];
__device__ float g_f1[2 * 1024];
__device__ float g_g1[2 * 1024];
__device__ float g_f2[2 * 4096];
__device__ float g_g2[2 * 4096];
__device__ float g_emd1r[2 * 1024];
__device__ float g_emd2r[2 * 4096];
__device__ float g_d1c[2 * 4096];
__device__ float g_d2c[2 * 512];
__device__ float g_d1f[2 * 4096];
__device__ float g_d2f[2 * 4096];

// ---------------- fast math helpers ----------------
__device__ __forceinline__ float ex2(float x) {
    float y; asm("ex2.approx.ftz.f32 %0, %1;" : "=f"(y) : "f"(x)); return y;
}
__device__ __forceinline__ float lg2(float x) {
    float y; asm("lg2.approx.f32 %0, %1;" : "=f"(y) : "f"(x)); return y;
}
__device__ __forceinline__ ull pack2(float a, float b) {
    ull r; asm("mov.b64 %0, {%1, %2};" : "=l"(r) : "f"(a), "f"(b)); return r;
}
__device__ __forceinline__ void unpack2(ull v, float& a, float& b) {
    asm("mov.b64 {%0, %1}, %2;" : "=f"(a), "=f"(b) : "l"(v));
}
__device__ __forceinline__ ull fma2(ull a, ull b, ull c) {
    ull d; asm("fma.rn.f32x2 %0, %1, %2, %3;" : "=l"(d) : "l"(a), "l"(b), "l"(c)); return d;
}
__device__ __forceinline__ ull add2(ull a, ull b) {
    ull d; asm("add.rn.f32x2 %0, %1, %2;" : "=l"(d) : "l"(a), "l"(b)); return d;
}
__device__ __forceinline__ void lds2u64(unsigned addr, ull& a, ull& b) {
    asm volatile("ld.shared.v2.u64 {%0, %1}, [%2];" : "=l"(a), "=l"(b) : "r"(addr));
}

// ---------------- FPS: R8 structure (2 cheap barriers, atomicMin) + tree max ----
#define FPS_T 256
__global__ __launch_bounds__(FPS_T) void fps_kernel(const float* __restrict__ gt) {
    extern __shared__ float sh[];
    float* SX = sh;
    float* SY = sh + 4096;
    float* SZ = sh + 8192;
    int* swm  = (int*)(sh + 12288);   // [8] per-warp max bits
    int* sIdx = (int*)(sh + 12296);   // [2] winner idx, parity dbl-buffered

    int b = blockIdx.x;
    const float* P = gt + b * 4096 * 3;
    float* outp = g_gtfps + b * 1024 * 3;
    int t = threadIdx.x, lane = t & 31, wid = t >> 5;

    const float4* P4 = (const float4*)P;
    for (int k = t; k < 3072; k += FPS_T) {
        float4 v = P4[k];
        int e = 4 * k;
        float c[4] = {v.x, v.y, v.z, v.w};
#pragma unroll
        for (int q = 0; q < 4; q++) {
            int ei = e + q;
            sh[(ei % 3) * 4096 + (ei / 3)] = c[q];
        }
    }
    if (t == 0) { sIdx[0] = 0x7FFFFFFF; sIdx[1] = 0x7FFFFFFF; }
    __syncthreads();

    int base = t * 16;                      // contiguous ownership -> exact tiebreak
    ull qx[8], qy[8], qz[8], qw[8];
    float dm[16];
#pragma unroll
    for (int j = 0; j < 8; j++) {
        float x0 = SX[base + 2 * j], x1 = SX[base + 2 * j + 1];
        float y0 = SY[base + 2 * j], y1 = SY[base + 2 * j + 1];
        float z0 = SZ[base + 2 * j], z1 = SZ[base + 2 * j + 1];
        qx[j] = pack2(x0, x1); qy[j] = pack2(y0, y1); qz[j] = pack2(z0, z1);
        qw[j] = pack2(fmaf(z0, z0, fmaf(y0, y0, x0 * x0)),
                      fmaf(z1, z1, fmaf(y1, y1, x1 * x1)));
        dm[2 * j] = 1e10f; dm[2 * j + 1] = 1e10f;
    }

    float lx = SX[0], ly = SY[0], lz = SZ[0];
    if (t == 0) { outp[0] = lx; outp[1] = ly; outp[2] = lz; }

    for (int step = 1; step < 1024; step++) {
        float ll = fmaf(lz, lz, fmaf(ly, ly, lx * lx));
        ull nx = pack2(-2.0f * lx, -2.0f * lx);
        ull ny = pack2(-2.0f * ly, -2.0f * ly);
        ull nz = pack2(-2.0f * lz, -2.0f * lz);
        ull l2 = pack2(ll, ll);
        float pm[8];                         // independent per-pair maxes
#pragma unroll
        for (int j = 0; j < 8; j++) {
            ull d = fma2(qx[j], nx, qw[j]);
            d = fma2(qy[j], ny, d);
            d = fma2(qz[j], nz, d);
            d = add2(d, l2);
            float d0, d1; unpack2(d, d0, d1);
            dm[2 * j]     = fminf(dm[2 * j], d0);
            dm[2 * j + 1] = fminf(dm[2 * j + 1], d1);
            pm[j] = fmaxf(dm[2 * j], dm[2 * j + 1]);
        }
        // tree max (depth 3) instead of 16-deep chain
        float a0 = fmaxf(pm[0], pm[1]), a1 = fmaxf(pm[2], pm[3]);
        float a2 = fmaxf(pm[4], pm[5]), a3 = fmaxf(pm[6], pm[7]);
        float mv = fmaxf(fmaxf(a0, a1), fmaxf(a2, a3));

        int mb = __float_as_int(mv);               // d>=0 -> bits monotone
        int M = __reduce_max_sync(0xffffffffu, mb);
        if (lane == 0) swm[wid] = M;
        __syncthreads();
        int MM = max(max(max(swm[0], swm[1]), max(swm[2], swm[3])),
                     max(max(swm[4], swm[5]), max(swm[6], swm[7])));
        if (mb == MM) {                            // winning thread(s) only
            float Mf = __int_as_float(MM);
            int idx = 0x7FFFFFFF;
#pragma unroll
            for (int j = 15; j >= 0; j--)
                if (dm[j] == Mf) idx = base + j;   // downward scan -> lowest idx
            atomicMin(&sIdx[step & 1], idx);
        }
        __syncthreads();
        int wi = sIdx[step & 1];
        lx = SX[wi]; ly = SY[wi]; lz = SZ[wi];
        if (t == 0) {
            outp[step * 3 + 0] = lx; outp[step * 3 + 1] = ly; outp[step * 3 + 2] = lz;
            sIdx[(step + 1) & 1] = 0x7FFFFFFF;     // reset other slot
        }
    }
}

// ---------------- pairwise kernel: 4 rows x 2-warp j-split, split A/B layout ----------------
// A region (8*Nq bytes): per pair p, 16B {x0,x1,y0,y1}; B region: {z0,z1,w0,w1}.
// MODE 0/1: xyz*TWOK2, w = K2*g - K2*|q|^2; MODE 2: raw coords, w=|q|^2.
// Warp w: row-group g=w>>1 (4 rows), j-half h=w&1; exact partial LSE, merged after 1 barrier.
template <int MODE, int NTT>
__global__ __launch_bounds__(NTT) void pair_kernel(
    const float* __restrict__ Pbase, int Np, int maskP, int strideP,
    const float* __restrict__ Qbase, int Nq, int maskQ, int strideQ,
    const float* __restrict__ vinBase, float* __restrict__ voutBase,
    float epsLogN, const int* __restrict__ itersPtr, int myIter)
{
    constexpr int ROWS = NTT / 16;
    constexpr int NW = NTT / 32;
    if (itersPtr && myIter >= *itersPtr) return;
    int b = blockIdx.y;
    const float* P = Pbase + b * strideP;
    const float* Q = Qbase + b * strideQ;
    const float* vin = vinBase ? (vinBase + b * Nq) : nullptr;

    extern __shared__ float sh[];
    float* shB = sh + 2 * Nq;
    float* shG = sh + 4 * Nq;
    __shared__ float s_pa[NW][4];
    __shared__ float s_pb[NW][4];
    __shared__ float s_pc[NW][4];

    for (int j = threadIdx.x; j < Nq; j += NTT) {
        int qj = j & maskQ;
        float qx = Q[qj * 3], qy = Q[qj * 3 + 1], qz = Q[qj * 3 + 2];
        float qw = fmaf(qz, qz, fmaf(qy, qy, qx * qx));
        int p = j >> 1, h2 = j & 1;
        if (MODE == 2) {
            sh[4 * p + h2]      = qx;
            sh[4 * p + 2 + h2]  = qy;
            shB[4 * p + h2]     = qz;
            shB[4 * p + 2 + h2] = qw;
        } else {
            float gv = vin ? vin[j] : 0.0f;
            sh[4 * p + h2]      = qx * TWOK2;
            sh[4 * p + 2 + h2]  = qy * TWOK2;
            shB[4 * p + h2]     = qz * TWOK2;
            shB[4 * p + 2 + h2] = fmaf(-K2, qw, gv * K2);
            if (MODE == 1) shG[j] = gv * K2;
        }
    }
    __syncthreads();

    int warp = threadIdx.x >> 5, lane = threadIdx.x & 31;
    int g = warp >> 1, h = warp & 1;
    int i0 = blockIdx.x * ROWS + g * 4;
    bool valid = i0 < Np;

    float px[4], py[4], pz[4], x2[4];
    unsigned sbase = (unsigned)__cvta_generic_to_shared(sh);
    unsigned aA0 = sbase + (unsigned)(h * 4 * Nq) + lane * 16;
    unsigned aB0 = aA0 + (unsigned)(8 * Nq);
    int iters = Nq >> 7;

    if (valid) {
#pragma unroll
        for (int r = 0; r < 4; r++) {
            int pi = (i0 + r) & maskP;
            px[r] = P[pi * 3]; py[r] = P[pi * 3 + 1]; pz[r] = P[pi * 3 + 2];
            x2[r] = fmaf(pz[r], pz[r], fmaf(py[r], py[r], px[r] * px[r]));
        }

        if (MODE == 2) {
            ull nx[4], ny[4], nz[4];
            float mn[4];
#pragma unroll
            for (int r = 0; r < 4; r++) {
                nx[r] = pack2(-2.0f * px[r], -2.0f * px[r]);
                ny[r] = pack2(-2.0f * py[r], -2.0f * py[r]);
                nz[r] = pack2(-2.0f * pz[r], -2.0f * pz[r]);
                mn[r] = 3.4e38f;
            }
            unsigned aA = aA0, aB = aB0;
#pragma unroll 4
            for (int k = 0; k < iters; k++, aA += 512, aB += 512) {
                ull x01, y01, z01, w01;
                lds2u64(aA, x01, y01);
                lds2u64(aB, z01, w01);
#pragma unroll
                for (int r = 0; r < 4; r++) {
                    ull acc = fma2(x01, nx[r], w01);
                    acc = fma2(y01, ny[r], acc);
                    acc = fma2(z01, nz[r], acc);
                    float t0, t1; unpack2(acc, t0, t1);
                    mn[r] = fminf(mn[r], fminf(t0, t1));
                }
            }
#pragma unroll
            for (int off = 16; off; off >>= 1)
#pragma unroll
                for (int r = 0; r < 4; r++)
                    mn[r] = fminf(mn[r], __shfl_xor_sync(0xffffffffu, mn[r], off));
            if (lane == 0)
#pragma unroll
                for (int r = 0; r < 4; r++) s_pa[warp][r] = mn[r];
        } else {
            ull vx[4], vy[4], vz[4];
#pragma unroll
            for (int r = 0; r < 4; r++) {
                vx[r] = pack2(px[r], px[r]);
                vy[r] = pack2(py[r], py[r]);
                vz[r] = pack2(pz[r], pz[r]);
            }
            float m[4];
#pragma unroll
            for (int r = 0; r < 4; r++) m[r] = -3.0e38f;
            {
                unsigned aA = aA0, aB = aB0;
#pragma unroll 4
                for (int k = 0; k < iters; k++, aA += 512, aB += 512) {
                    ull x01, y01, z01, w01;
                    lds2u64(aA, x01, y01);
                    lds2u64(aB, z01, w01);
#pragma unroll
                    for (int r = 0; r < 4; r++) {
                        ull acc = fma2(x01, vx[r], w01);
                        acc = fma2(y01, vy[r], acc);
                        acc = fma2(z01, vz[r], acc);
                        float t0, t1; unpack2(acc, t0, t1);
                        m[r] = fmaxf(m[r], fmaxf(t0, t1));
                    }
                }
#pragma unroll
                for (int off = 16; off; off >>= 1)
#pragma unroll
                    for (int r = 0; r < 4; r++)
                        m[r] = fmaxf(m[r], __shfl_xor_sync(0xffffffffu, m[r], off));
            }
            ull nm[4];
#pragma unroll
            for (int r = 0; r < 4; r++) nm[r] = pack2(-m[r], -m[r]);

            if (MODE == 0) {
                float s[4] = {0.0f, 0.0f, 0.0f, 0.0f};
                unsigned aA = aA0, aB = aB0;
#pragma unroll 4
                for (int k = 0; k < iters; k++, aA += 512, aB += 512) {
                    ull x01, y01, z01, w01;
                    lds2u64(aA, x01, y01);
                    lds2u64(aB, z01, w01);
#pragma unroll
                    for (int r = 0; r < 4; r++) {
                        ull acc = fma2(x01, vx[r], w01);
                        acc = fma2(y01, vy[r], acc);
                        acc = fma2(z01, vz[r], acc);
                        acc = add2(acc, nm[r]);
                        float t0, t1; unpack2(acc, t0, t1);
                        s[r] += ex2(t0) + ex2(t1);
                    }
                }
#pragma unroll
                for (int off = 16; off; off >>= 1)
#pragma unroll
                    for (int r = 0; r < 4; r++)
                        s[r] += __shfl_xor_sync(0xffffffffu, s[r], off);
                if (lane == 0)
#pragma unroll
                    for (int r = 0; r < 4; r++) {
                        s_pa[warp][r] = m[r];
                        s_pb[warp][r] = s[r];
                    }
            } else {
                float s[4] = {0.0f, 0.0f, 0.0f, 0.0f};
                float sc[4] = {0.0f, 0.0f, 0.0f, 0.0f};
                unsigned aA = aA0, aB = aB0;
                unsigned aG = sbase + 16u * (unsigned)Nq + (unsigned)(h * 2 * Nq) + lane * 8;
#pragma unroll 2
                for (int k = 0; k < iters; k++, aA += 512, aB += 512, aG += 256) {
                    ull x01, y01, z01, w01;
                    lds2u64(aA, x01, y01);
                    lds2u64(aB, z01, w01);
                    float2 gv;
                    asm volatile("ld.shared.v2.f32 {%0, %1}, [%2];"
                                 : "=f"(gv.x), "=f"(gv.y) : "r"(aG));
#pragma unroll
                    for (int r = 0; r < 4; r++) {
                        ull acc = fma2(x01, vx[r], w01);
                        acc = fma2(y01, vy[r], acc);
                        acc = fma2(z01, vz[r], acc);
                        acc = add2(acc, nm[r]);
                        float t0, t1; unpack2(acc, t0, t1);
                        float e0 = ex2(t0), e1 = ex2(t1);
                        float C0 = fmaf(gv.x - (t0 + m[r]), EPS_LN2, x2[r]);
                        float C1 = fmaf(gv.y - (t1 + m[r]), EPS_LN2, x2[r]);
                        s[r] += e0 + e1;
                        sc[r] = fmaf(e0, C0, sc[r]);
                        sc[r] = fmaf(e1, C1, sc[r]);
                    }
                }
#pragma unroll
                for (int off = 16; off; off >>= 1)
#pragma unroll
                    for (int r = 0; r < 4; r++) {
                        s[r]  += __shfl_xor_sync(0xffffffffu, s[r], off);
                        sc[r] += __shfl_xor_sync(0xffffffffu, sc[r], off);
                    }
                if (lane == 0)
#pragma unroll
                    for (int r = 0; r < 4; r++) {
                        s_pa[warp][r] = m[r];
                        s_pb[warp][r] = s[r];
                        s_pc[warp][r] = sc[r];
                    }
            }
        }
    }
    __syncthreads();

    if (valid && h == 0 && lane == 0) {
#pragma unroll
        for (int r = 0; r < 4; r++) {
            if (MODE == 2) {
                float mn = fminf(s_pa[warp][r], s_pa[warp + 1][r]);
                voutBase[b * Np + i0 + r] = fmaxf(mn + x2[r], 0.0f);
            } else {
                float m0 = s_pa[warp][r], m1 = s_pa[warp + 1][r];
                float s0 = s_pb[warp][r], s1 = s_pb[warp + 1][r];
                float M = fmaxf(m0, m1);
                float e0 = ex2(m0 - M), e1 = ex2(m1 - M);
                float s = fmaf(s0, e0, s1 * e1);
                if (MODE == 0) {
                    voutBase[b * Np + i0 + r] =
                        fmaf(-EPS_LN2, (M - K2 * x2[r]) + lg2(s), -epsLogN);
                } else {
                    float sc = fmaf(s_pc[warp][r], e0, s_pc[warp + 1][r] * e1);
                    voutBase[b * Np + i0 + r] = sqrtf(sc / s);
                }
            }
        }
    }
}

// ---------------- reductions / final scalar outputs ----------------
__device__ __forceinline__ float blk_sum(float v, float* shp) {
    int lane = threadIdx.x & 31, wid = threadIdx.x >> 5;
#pragma unroll
    for (int off = 16; off; off >>= 1) v += __shfl_xor_sync(0xffffffffu, v, off);
    if (lane == 0) shp[wid] = v;
    __syncthreads();
    float r = 0.0f;
    if (wid == 0) {
        r = shp[lane];
#pragma unroll
        for (int off = 16; off; off >>= 1) r += __shfl_xor_sync(0xffffffffu, r, off);
    }
    __syncthreads();
    return r;
}

__global__ __launch_bounds__(1024) void finalize_kernel(float* __restrict__ out) {
    __shared__ float shp[32];
    int b = blockIdx.x;
    int t = threadIdx.x;
    const int BASE = 27648;

    float v = g_emd1r[b * 1024 + t];
    v = blk_sum(v, shp);
    if (t == 0) out[BASE + 0 + b] = v * (1.0f / 1024.0f);

    v = 0.0f;
    for (int i = t; i < 4096; i += 1024) v += g_emd2r[b * 4096 + i];
    v = blk_sum(v, shp);
    if (t == 0) out[BASE + 2 + b] = v * (1.0f / 4096.0f);

    float vs = 0.0f, vt = 0.0f;
    for (int i = t; i < 4096; i += 1024) { float d = g_d1c[b * 4096 + i]; vs += sqrtf(d); vt += d; }
    vs = blk_sum(vs, shp); vt = blk_sum(vt, shp);
    float vs2 = 0.0f, vt2 = 0.0f;
    if (t < 512) { float d = g_d2c[b * 512 + t]; vs2 = sqrtf(d); vt2 = d; }
    vs2 = blk_sum(vs2, shp); vt2 = blk_sum(vt2, shp);
    if (t == 0) {
        out[BASE + 4 + b] = (vs * (1.0f / 4096.0f) + vs2 * (1.0f / 512.0f)) * 0.5f;
        out[BASE + 8 + b] = vt * (1.0f / 4096.0f) + vt2 * (1.0f / 512.0f);
    }

    vs = 0.0f; vt = 0.0f;
    for (int i = t; i < 4096; i += 1024) { float d = g_d1f[b * 4096 + i]; vs += sqrtf(d); vt += d; }
    vs = blk_sum(vs, shp); vt = blk_sum(vt, shp);
    vs2 = 0.0f; vt2 = 0.0f;
    for (int i = t; i < 4096; i += 1024) { float d = g_d2f[b * 4096 + i]; vs2 += sqrtf(d); vt2 += d; }
    vs2 = blk_sum(vs2, shp); vt2 = blk_sum(vt2, shp);
    if (t == 0) {
        out[BASE + 6 + b]  = (vs + vs2) * (1.0f / 4096.0f) * 0.5f;
        out[BASE + 10 + b] = (vt + vt2) * (1.0f / 4096.0f);
    }
}

// ---------------- launch ----------------
extern "C" void kernel_launch(void* const* d_in, const int* in_sizes, int n_in,
                              void* d_out, int out_size) {
    const float* coarse = (const float*)d_in[0];
    const float* fine   = (const float*)d_in[1];
    const float* gt     = (const float*)d_in[2];
    const int*   iters  = (const int*)d_in[3];
    float* out = (float*)d_out;

    static cudaStream_t s1 = nullptr;
    static cudaEvent_t evFork = nullptr, evJoin = nullptr;
    if (!s1) {
        cudaStreamCreateWithFlags(&s1, cudaStreamNonBlocking);
        cudaEventCreateWithFlags(&evFork, cudaEventDisableTiming);
        cudaEventCreateWithFlags(&evJoin, cudaEventDisableTiming);
        cudaFuncSetAttribute((const void*)pair_kernel<0,896>, cudaFuncAttributeMaxDynamicSharedMemorySize, 84000);
        cudaFuncSetAttribute((const void*)pair_kernel<1,896>, cudaFuncAttributeMaxDynamicSharedMemorySize, 84000);
        cudaFuncSetAttribute((const void*)pair_kernel<2,896>, cudaFuncAttributeMaxDynamicSharedMemorySize, 84000);
        cudaFuncSetAttribute((const void*)pair_kernel<0,256>, cudaFuncAttributeMaxDynamicSharedMemorySize, 84000);
        cudaFuncSetAttribute((const void*)pair_kernel<1,256>, cudaFuncAttributeMaxDynamicSharedMemorySize, 84000);
        cudaFuncSetAttribute((const void*)pair_kernel<2,256>, cudaFuncAttributeMaxDynamicSharedMemorySize, 84000);
        cudaFuncSetAttribute((const void*)fps_kernel, cudaFuncAttributeMaxDynamicSharedMemorySize, 49400);
    }

    float *gtfps, *f1, *g1, *f2, *g2, *e1r, *e2r, *d1c, *d2c, *d1f, *d2f;
    cudaGetSymbolAddress((void**)&gtfps, g_gtfps);
    cudaGetSymbolAddress((void**)&f1, g_f1);
    cudaGetSymbolAddress((void**)&g1, g_g1);
    cudaGetSymbolAddress((void**)&f2, g_f2);
    cudaGetSymbolAddress((void**)&g2, g_g2);
    cudaGetSymbolAddress((void**)&e1r, g_emd1r);
    cudaGetSymbolAddress((void**)&e2r, g_emd2r);
    cudaGetSymbolAddress((void**)&d1c, g_d1c);
    cudaGetSymbolAddress((void**)&d2c, g_d2c);
    cudaGetSymbolAddress((void**)&d1f, g_d1f);
    cudaGetSymbolAddress((void**)&d2f, g_d2f);

    // ---- fork: FPS + EMD1 on s1 ----
    cudaEventRecord(evFork, 0);
    cudaStreamWaitEvent(s1, evFork, 0);
    fps_kernel<<<2, FPS_T, 49400, s1>>>(gt);

    cudaMemcpyAsync(out,        coarse, 2 * 512 * 3 * sizeof(float),  cudaMemcpyDeviceToDevice);
    cudaMemcpyAsync(out + 3072, fine,   2 * 4096 * 3 * sizeof(float), cudaMemcpyDeviceToDevice);

    const int GX4 = (4096 + 55) / 56;   // 74 -> grid (74,2) = 148 = 1 block/SM
    const int GX1 = 1024 / 16;          // 64 (NTT=256, 16 rows/block)
    const int GXC = 512 / 16;           // 32

    // ---- stream 0: EMD2 chain ----
    for (int it = 0; it < 4; it++) {
        pair_kernel<0,896><<<dim3(GX4, 2), 896, 4096 * 16>>>(
            fine, 4096, IDENT_MASK, 4096 * 3, gt, 4096, IDENT_MASK, 4096 * 3,
            it == 0 ? nullptr : g2, f2, EPSLOG4096, iters, it);
        pair_kernel<0,896><<<dim3(GX4, 2), 896, 4096 * 16>>>(
            gt, 4096, IDENT_MASK, 4096 * 3, fine, 4096, IDENT_MASK, 4096 * 3,
            f2, g2, EPSLOG4096, iters, it);
    }
    pair_kernel<1,896><<<dim3(GX4, 2), 896, 4096 * 20>>>(
        fine, 4096, IDENT_MASK, 4096 * 3, gt, 4096, IDENT_MASK, 4096 * 3,
        g2, e2r, 0.0f, nullptr, 0);

    // ---- stream 0: chamfers ----
    pair_kernel<2,896><<<dim3(GX4, 2), 896, 4096 * 16>>>(
        fine, 4096, IDENT_MASK, 4096 * 3, gt, 4096, IDENT_MASK, 4096 * 3,
        nullptr, d2f, 0.0f, nullptr, 0);
    pair_kernel<2,896><<<dim3(GX4, 2), 896, 4096 * 16>>>(
        gt, 4096, IDENT_MASK, 4096 * 3, fine, 4096, IDENT_MASK, 4096 * 3,
        nullptr, d1f, 0.0f, nullptr, 0);
    pair_kernel<2,896><<<dim3(GX4, 2), 896, 512 * 16>>>(
        gt, 4096, IDENT_MASK, 4096 * 3, coarse, 512, IDENT_MASK, 512 * 3,
        nullptr, d1c, 0.0f, nullptr, 0);
    pair_kernel<2,256><<<dim3(GXC, 2), 256, 4096 * 16>>>(
        coarse, 512, IDENT_MASK, 512 * 3, gt, 4096, IDENT_MASK, 4096 * 3,
        nullptr, d2c, 0.0f, nullptr, 0);

    // ---- s1: EMD1 chain (after FPS) ----
    for (int it = 0; it < 4; it++) {
        pair_kernel<0,256><<<dim3(GX1, 2), 256, 1024 * 16, s1>>>(
            coarse, 1024, 511, 512 * 3, gtfps, 1024, IDENT_MASK, 1024 * 3,
            it == 0 ? nullptr : g1, f1, EPSLOG1024, iters, it);
        pair_kernel<0,256><<<dim3(GX1, 2), 256, 1024 * 16, s1>>>(
            gtfps, 1024, IDENT_MASK, 1024 * 3, coarse, 1024, 511, 512 * 3,
            f1, g1, EPSLOG1024, iters, it);
    }
    pair_kernel<1,256><<<dim3(GX1, 2), 256, 1024 * 20, s1>>>(
        coarse, 1024, 511, 512 * 3, gtfps, 1024, IDENT_MASK, 1024 * 3,
        g1, e1r, 0.0f, nullptr, 0);

    // ---- join, finalize ----
    cudaEventRecord(evJoin, s1);
    cudaStreamWaitEvent(0, evJoin, 0);
    finalize_kernel<<<2, 1024>>>(out);
}

// round 17
// speedup vs baseline: 1.2478x; 1.0574x over previous
#include <cuda_runtime.h>
#include <math.h>
#include <stdint.h>

// ---------------- constants ----------------
#define K2        72.13475204444817f     // (1/EPS)*log2(e)
#define TWOK2     144.26950408889634f    // 2*K2
#define EPS_LN2   0.013862943611198906f  // EPS*ln(2) == 1/K2
#define EPSLOG1024 0.13862943611198905f
#define EPSLOG4096 0.16635532333438687f
#define IDENT_MASK 0x7FFFFFFF
typedef unsigned long long ull;

// ---------------- scratch ----------------
__device__ float g_gtfps[2 * 1024 * 3];
__device__ float g_f1[2 * 1024];
__device__ float g_g1[2 * 1024];
__device__ float g_f2[2 * 4096];
__device__ float g_g2[2 * 4096];
__device__ float g_emd1r[2 * 1024];
__device__ float g_emd2r[2 * 4096];
__device__ float g_d1c[2 * 4096];
__device__ float g_d2c[2 * 512];
__device__ float g_d1f[2 * 4096];
__device__ float g_d2f[2 * 4096];

// ---------------- fast math helpers ----------------
__device__ __forceinline__ float ex2(float x) {
    float y; asm("ex2.approx.ftz.f32 %0, %1;" : "=f"(y) : "f"(x)); return y;
}
__device__ __forceinline__ float lg2(float x) {
    float y; asm("lg2.approx.f32 %0, %1;" : "=f"(y) : "f"(x)); return y;
}
__device__ __forceinline__ ull pack2(float a, float b) {
    ull r; asm("mov.b64 %0, {%1, %2};" : "=l"(r) : "f"(a), "f"(b)); return r;
}
__device__ __forceinline__ void unpack2(ull v, float& a, float& b) {
    asm("mov.b64 {%0, %1}, %2;" : "=f"(a), "=f"(b) : "l"(v));
}
__device__ __forceinline__ ull fma2(ull a, ull b, ull c) {
    ull d; asm("fma.rn.f32x2 %0, %1, %2, %3;" : "=l"(d) : "l"(a), "l"(b), "l"(c)); return d;
}
__device__ __forceinline__ ull add2(ull a, ull b) {
    ull d; asm("add.rn.f32x2 %0, %1, %2;" : "=l"(d) : "l"(a), "l"(b)); return d;
}
__device__ __forceinline__ void lds2u64(unsigned addr, ull& a, ull& b) {
    asm volatile("ld.shared.v2.u64 {%0, %1}, [%2];" : "=l"(a), "=l"(b) : "r"(addr));
}

// ---------------- FPS: AoS winner fetch, monotone key, vector merge ----------------
#define FPS_T 256
__global__ __launch_bounds__(FPS_T) void fps_kernel(const float* __restrict__ gt) {
    extern __shared__ float sh[];
    float4* SP = (float4*)sh;             // [4096] {x, y, z, |p|^2}
    int* swm = (int*)(sh + 16384);        // [8] per-warp max bits
    unsigned* sKey = (unsigned*)(swm + 8);// single monotone key

    int b = blockIdx.x;
    const float* P = gt + b * 4096 * 3;
    float* outp = g_gtfps + b * 1024 * 3;
    int t = threadIdx.x, lane = t & 31, wid = t >> 5;

    // coalesced load -> AoS scatter
    const float4* P4 = (const float4*)P;
    for (int k = t; k < 3072; k += FPS_T) {
        float4 v = P4[k];
        int e = 4 * k;
        float c[4] = {v.x, v.y, v.z, v.w};
#pragma unroll
        for (int q = 0; q < 4; q++) {
            int ei = e + q;
            ((float*)&SP[ei / 3])[ei % 3] = c[q];
        }
    }
    if (t == 0) *sKey = 0u;
    __syncthreads();
    for (int i = t; i < 4096; i += FPS_T) {
        float4 p = SP[i];
        SP[i].w = fmaf(p.z, p.z, fmaf(p.y, p.y, p.x * p.x));
    }
    __syncthreads();

    int base = t * 16;                    // contiguous ownership -> exact tiebreak
    ull qx[8], qy[8], qz[8], qw[8];
    float dm[16];
#pragma unroll
    for (int j = 0; j < 8; j++) {
        float4 p0 = SP[base + 2 * j], p1 = SP[base + 2 * j + 1];
        qx[j] = pack2(p0.x, p1.x); qy[j] = pack2(p0.y, p1.y); qz[j] = pack2(p0.z, p1.z);
        qw[j] = pack2(p0.w, p1.w);
        dm[2 * j] = 1e10f; dm[2 * j + 1] = 1e10f;
    }

    float4 L = SP[0];
    if (t == 0) { outp[0] = L.x; outp[1] = L.y; outp[2] = L.z; }

    for (int step = 1; step < 1024; step++) {
        ull nx = pack2(-2.0f * L.x, -2.0f * L.x);
        ull ny = pack2(-2.0f * L.y, -2.0f * L.y);
        ull nz = pack2(-2.0f * L.z, -2.0f * L.z);
        ull l2 = pack2(L.w, L.w);          // |L|^2 free from AoS .w
        float pm[8];
#pragma unroll
        for (int j = 0; j < 8; j++) {
            ull d = fma2(qx[j], nx, qw[j]);
            d = fma2(qy[j], ny, d);
            d = fma2(qz[j], nz, d);
            d = add2(d, l2);
            float d0, d1; unpack2(d, d0, d1);
            dm[2 * j]     = fminf(dm[2 * j], d0);
            dm[2 * j + 1] = fminf(dm[2 * j + 1], d1);
            pm[j] = fmaxf(dm[2 * j], dm[2 * j + 1]);
        }
        float a0 = fmaxf(pm[0], pm[1]), a1 = fmaxf(pm[2], pm[3]);
        float a2 = fmaxf(pm[4], pm[5]), a3 = fmaxf(pm[6], pm[7]);
        float mv = fmaxf(fmaxf(a0, a1), fmaxf(a2, a3));

        int mb = __float_as_int(mv);               // d>=0 -> bits monotone
        int M = __reduce_max_sync(0xffffffffu, mb);
        if (lane == 0) swm[wid] = M;
        __syncthreads();
        int4 wa = *(int4*)swm;
        int4 wb = *(int4*)(swm + 4);
        int MM = max(max(max(wa.x, wa.y), max(wa.z, wa.w)),
                     max(max(wb.x, wb.y), max(wb.z, wb.w)));
        if (mb == MM) {                            // winning thread(s) only
            float Mf = __int_as_float(MM);
            int idx = 0;
#pragma unroll
            for (int j = 15; j >= 0; j--)
                if (dm[j] == Mf) idx = base + j;   // downward scan -> lowest idx
            atomicMax(sKey, ((unsigned)step << 12) | (4095u - (unsigned)idx));
        }
        __syncthreads();
        int wi = 4095 - (int)(*sKey & 4095u);
        L = SP[wi];                                // single LDS.128
        if (t == 0) {
            outp[step * 3 + 0] = L.x; outp[step * 3 + 1] = L.y; outp[step * 3 + 2] = L.z;
        }
    }
}

// ---------------- pairwise kernel: 4 rows x 2-warp j-split, split A/B layout ----------------
// A region (8*Nq bytes): per pair p, 16B {x0,x1,y0,y1}; B region: {z0,z1,w0,w1}.
// MODE 0/1: xyz*TWOK2, w = K2*g - K2*|q|^2; MODE 2: raw coords, w=|q|^2.
template <int MODE, int NTT>
__global__ __launch_bounds__(NTT) void pair_kernel(
    const float* __restrict__ Pbase, int Np, int maskP, int strideP,
    const float* __restrict__ Qbase, int Nq, int maskQ, int strideQ,
    const float* __restrict__ vinBase, float* __restrict__ voutBase,
    float epsLogN, const int* __restrict__ itersPtr, int myIter)
{
    constexpr int ROWS = NTT / 16;
    constexpr int NW = NTT / 32;
    if (itersPtr && myIter >= *itersPtr) return;
    int b = blockIdx.y;
    const float* P = Pbase + b * strideP;
    const float* Q = Qbase + b * strideQ;
    const float* vin = vinBase ? (vinBase + b * Nq) : nullptr;

    extern __shared__ float sh[];
    float* shB = sh + 2 * Nq;
    float* shG = sh + 4 * Nq;
    __shared__ float s_pa[NW][4];
    __shared__ float s_pb[NW][4];
    __shared__ float s_pc[NW][4];

    for (int j = threadIdx.x; j < Nq; j += NTT) {
        int qj = j & maskQ;
        float qx = Q[qj * 3], qy = Q[qj * 3 + 1], qz = Q[qj * 3 + 2];
        float qw = fmaf(qz, qz, fmaf(qy, qy, qx * qx));
        int p = j >> 1, h2 = j & 1;
        if (MODE == 2) {
            sh[4 * p + h2]      = qx;
            sh[4 * p + 2 + h2]  = qy;
            shB[4 * p + h2]     = qz;
            shB[4 * p + 2 + h2] = qw;
        } else {
            float gv = vin ? vin[j] : 0.0f;
            sh[4 * p + h2]      = qx * TWOK2;
            sh[4 * p + 2 + h2]  = qy * TWOK2;
            shB[4 * p + h2]     = qz * TWOK2;
            shB[4 * p + 2 + h2] = fmaf(-K2, qw, gv * K2);
            if (MODE == 1) shG[j] = gv * K2;
        }
    }
    __syncthreads();

    int warp = threadIdx.x >> 5, lane = threadIdx.x & 31;
    int g = warp >> 1, h = warp & 1;
    int i0 = blockIdx.x * ROWS + g * 4;
    bool valid = i0 < Np;

    float px[4], py[4], pz[4], x2[4];
    unsigned sbase = (unsigned)__cvta_generic_to_shared(sh);
    unsigned aA0 = sbase + (unsigned)(h * 4 * Nq) + lane * 16;
    unsigned aB0 = aA0 + (unsigned)(8 * Nq);
    int iters = Nq >> 7;

    if (valid) {
#pragma unroll
        for (int r = 0; r < 4; r++) {
            int pi = (i0 + r) & maskP;
            px[r] = P[pi * 3]; py[r] = P[pi * 3 + 1]; pz[r] = P[pi * 3 + 2];
            x2[r] = fmaf(pz[r], pz[r], fmaf(py[r], py[r], px[r] * px[r]));
        }

        if (MODE == 2) {
            ull nx[4], ny[4], nz[4];
            float mn[4];
#pragma unroll
            for (int r = 0; r < 4; r++) {
                nx[r] = pack2(-2.0f * px[r], -2.0f * px[r]);
                ny[r] = pack2(-2.0f * py[r], -2.0f * py[r]);
                nz[r] = pack2(-2.0f * pz[r], -2.0f * pz[r]);
                mn[r] = 3.4e38f;
            }
            unsigned aA = aA0, aB = aB0;
#pragma unroll 4
            for (int k = 0; k < iters; k++, aA += 512, aB += 512) {
                ull x01, y01, z01, w01;
                lds2u64(aA, x01, y01);
                lds2u64(aB, z01, w01);
#pragma unroll
                for (int r = 0; r < 4; r++) {
                    ull acc = fma2(x01, nx[r], w01);
                    acc = fma2(y01, ny[r], acc);
                    acc = fma2(z01, nz[r], acc);
                    float t0, t1; unpack2(acc, t0, t1);
                    mn[r] = fminf(mn[r], fminf(t0, t1));
                }
            }
#pragma unroll
            for (int off = 16; off; off >>= 1)
#pragma unroll
                for (int r = 0; r < 4; r++)
                    mn[r] = fminf(mn[r], __shfl_xor_sync(0xffffffffu, mn[r], off));
            if (lane == 0)
#pragma unroll
                for (int r = 0; r < 4; r++) s_pa[warp][r] = mn[r];
        } else {
            ull vx[4], vy[4], vz[4];
#pragma unroll
            for (int r = 0; r < 4; r++) {
                vx[r] = pack2(px[r], px[r]);
                vy[r] = pack2(py[r], py[r]);
                vz[r] = pack2(pz[r], pz[r]);
            }
            float m[4];
#pragma unroll
            for (int r = 0; r < 4; r++) m[r] = -3.0e38f;
            {
                unsigned aA = aA0, aB = aB0;
#pragma unroll 4
                for (int k = 0; k < iters; k++, aA += 512, aB += 512) {
                    ull x01, y01, z01, w01;
                    lds2u64(aA, x01, y01);
                    lds2u64(aB, z01, w01);
#pragma unroll
                    for (int r = 0; r < 4; r++) {
                        ull acc = fma2(x01, vx[r], w01);
                        acc = fma2(y01, vy[r], acc);
                        acc = fma2(z01, vz[r], acc);
                        float t0, t1; unpack2(acc, t0, t1);
                        m[r] = fmaxf(m[r], fmaxf(t0, t1));
                    }
                }
#pragma unroll
                for (int off = 16; off; off >>= 1)
#pragma unroll
                    for (int r = 0; r < 4; r++)
                        m[r] = fmaxf(m[r], __shfl_xor_sync(0xffffffffu, m[r], off));
            }
            ull nm[4];
#pragma unroll
            for (int r = 0; r < 4; r++) nm[r] = pack2(-m[r], -m[r]);

            if (MODE == 0) {
                float s[4] = {0.0f, 0.0f, 0.0f, 0.0f};
                unsigned aA = aA0, aB = aB0;
#pragma unroll 4
                for (int k = 0; k < iters; k++, aA += 512, aB += 512) {
                    ull x01, y01, z01, w01;
                    lds2u64(aA, x01, y01);
                    lds2u64(aB, z01, w01);
#pragma unroll
                    for (int r = 0; r < 4; r++) {
                        ull acc = fma2(x01, vx[r], w01);
                        acc = fma2(y01, vy[r], acc);
                        acc = fma2(z01, vz[r], acc);
                        acc = add2(acc, nm[r]);
                        float t0, t1; unpack2(acc, t0, t1);
                        s[r] += ex2(t0) + ex2(t1);
                    }
                }
#pragma unroll
                for (int off = 16; off; off >>= 1)
#pragma unroll
                    for (int r = 0; r < 4; r++)
                        s[r] += __shfl_xor_sync(0xffffffffu, s[r], off);
                if (lane == 0)
#pragma unroll
                    for (int r = 0; r < 4; r++) {
                        s_pa[warp][r] = m[r];
                        s_pb[warp][r] = s[r];
                    }
            } else {
                float s[4] = {0.0f, 0.0f, 0.0f, 0.0f};
                float sc[4] = {0.0f, 0.0f, 0.0f, 0.0f};
                unsigned aA = aA0, aB = aB0;
                unsigned aG = sbase + 16u * (unsigned)Nq + (unsigned)(h * 2 * Nq) + lane * 8;
#pragma unroll 2
                for (int k = 0; k < iters; k++, aA += 512, aB += 512, aG += 256) {
                    ull x01, y01, z01, w01;
                    lds2u64(aA, x01, y01);
                    lds2u64(aB, z01, w01);
                    float2 gv;
                    asm volatile("ld.shared.v2.f32 {%0, %1}, [%2];"
                                 : "=f"(gv.x), "=f"(gv.y) : "r"(aG));
#pragma unroll
                    for (int r = 0; r < 4; r++) {
                        ull acc = fma2(x01, vx[r], w01);
                        acc = fma2(y01, vy[r], acc);
                        acc = fma2(z01, vz[r], acc);
                        acc = add2(acc, nm[r]);
                        float t0, t1; unpack2(acc, t0, t1);
                        float e0 = ex2(t0), e1 = ex2(t1);
                        float C0 = fmaf(gv.x - (t0 + m[r]), EPS_LN2, x2[r]);
                        float C1 = fmaf(gv.y - (t1 + m[r]), EPS_LN2, x2[r]);
                        s[r] += e0 + e1;
                        sc[r] = fmaf(e0, C0, sc[r]);
                        sc[r] = fmaf(e1, C1, sc[r]);
                    }
                }
#pragma unroll
                for (int off = 16; off; off >>= 1)
#pragma unroll
                    for (int r = 0; r < 4; r++) {
                        s[r]  += __shfl_xor_sync(0xffffffffu, s[r], off);
                        sc[r] += __shfl_xor_sync(0xffffffffu, sc[r], off);
                    }
                if (lane == 0)
#pragma unroll
                    for (int r = 0; r < 4; r++) {
                        s_pa[warp][r] = m[r];
                        s_pb[warp][r] = s[r];
                        s_pc[warp][r] = sc[r];
                    }
            }
        }
    }
    __syncthreads();

    if (valid && h == 0 && lane == 0) {
#pragma unroll
        for (int r = 0; r < 4; r++) {
            if (MODE == 2) {
                float mn = fminf(s_pa[warp][r], s_pa[warp + 1][r]);
                voutBase[b * Np + i0 + r] = fmaxf(mn + x2[r], 0.0f);
            } else {
                float m0 = s_pa[warp][r], m1 = s_pa[warp + 1][r];
                float s0 = s_pb[warp][r], s1 = s_pb[warp + 1][r];
                float M = fmaxf(m0, m1);
                float e0 = ex2(m0 - M), e1 = ex2(m1 - M);
                float s = fmaf(s0, e0, s1 * e1);
                if (MODE == 0) {
                    voutBase[b * Np + i0 + r] =
                        fmaf(-EPS_LN2, (M - K2 * x2[r]) + lg2(s), -epsLogN);
                } else {
                    float sc = fmaf(s_pc[warp][r], e0, s_pc[warp + 1][r] * e1);
                    voutBase[b * Np + i0 + r] = sqrtf(sc / s);
                }
            }
        }
    }
}

// ---------------- reductions / final scalar outputs ----------------
__device__ __forceinline__ float blk_sum(float v, float* shp) {
    int lane = threadIdx.x & 31, wid = threadIdx.x >> 5;
#pragma unroll
    for (int off = 16; off; off >>= 1) v += __shfl_xor_sync(0xffffffffu, v, off);
    if (lane == 0) shp[wid] = v;
    __syncthreads();
    float r = 0.0f;
    if (wid == 0) {
        r = shp[lane];
#pragma unroll
        for (int off = 16; off; off >>= 1) r += __shfl_xor_sync(0xffffffffu, r, off);
    }
    __syncthreads();
    return r;
}

__global__ __launch_bounds__(1024) void finalize_kernel(float* __restrict__ out) {
    __shared__ float shp[32];
    int b = blockIdx.x;
    int t = threadIdx.x;
    const int BASE = 27648;

    float v = g_emd1r[b * 1024 + t];
    v = blk_sum(v, shp);
    if (t == 0) out[BASE + 0 + b] = v * (1.0f / 1024.0f);

    v = 0.0f;
    for (int i = t; i < 4096; i += 1024) v += g_emd2r[b * 4096 + i];
    v = blk_sum(v, shp);
    if (t == 0) out[BASE + 2 + b] = v * (1.0f / 4096.0f);

    float vs = 0.0f, vt = 0.0f;
    for (int i = t; i < 4096; i += 1024) { float d = g_d1c[b * 4096 + i]; vs += sqrtf(d); vt += d; }
    vs = blk_sum(vs, shp); vt = blk_sum(vt, shp);
    float vs2 = 0.0f, vt2 = 0.0f;
    if (t < 512) { float d = g_d2c[b * 512 + t]; vs2 = sqrtf(d); vt2 = d; }
    vs2 = blk_sum(vs2, shp); vt2 = blk_sum(vt2, shp);
    if (t == 0) {
        out[BASE + 4 + b] = (vs * (1.0f / 4096.0f) + vs2 * (1.0f / 512.0f)) * 0.5f;
        out[BASE + 8 + b] = vt * (1.0f / 4096.0f) + vt2 * (1.0f / 512.0f);
    }

    vs = 0.0f; vt = 0.0f;
    for (int i = t; i < 4096; i += 1024) { float d = g_d1f[b * 4096 + i]; vs += sqrtf(d); vt += d; }
    vs = blk_sum(vs, shp); vt = blk_sum(vt, shp);
    vs2 = 0.0f; vt2 = 0.0f;
    for (int i = t; i < 4096; i += 1024) { float d = g_d2f[b * 4096 + i]; vs2 += sqrtf(d); vt2 += d; }
    vs2 = blk_sum(vs2, shp); vt2 = blk_sum(vt2, shp);
    if (t == 0) {
        out[BASE + 6 + b]  = (vs + vs2) * (1.0f / 4096.0f) * 0.5f;
        out[BASE + 10 + b] = (vt + vt2) * (1.0f / 4096.0f);
    }
}

// ---------------- launch ----------------
extern "C" void kernel_launch(void* const* d_in, const int* in_sizes, int n_in,
                              void* d_out, int out_size) {
    const float* coarse = (const float*)d_in[0];
    const float* fine   = (const float*)d_in[1];
    const float* gt     = (const float*)d_in[2];
    const int*   iters  = (const int*)d_in[3];
    float* out = (float*)d_out;

    static cudaStream_t s1 = nullptr;
    static cudaEvent_t evFork = nullptr, evJoin = nullptr;
    if (!s1) {
        cudaStreamCreateWithFlags(&s1, cudaStreamNonBlocking);
        cudaEventCreateWithFlags(&evFork, cudaEventDisableTiming);
        cudaEventCreateWithFlags(&evJoin, cudaEventDisableTiming);
        cudaFuncSetAttribute((const void*)pair_kernel<0,896>, cudaFuncAttributeMaxDynamicSharedMemorySize, 84000);
        cudaFuncSetAttribute((const void*)pair_kernel<1,896>, cudaFuncAttributeMaxDynamicSharedMemorySize, 84000);
        cudaFuncSetAttribute((const void*)pair_kernel<2,896>, cudaFuncAttributeMaxDynamicSharedMemorySize, 84000);
        cudaFuncSetAttribute((const void*)pair_kernel<0,256>, cudaFuncAttributeMaxDynamicSharedMemorySize, 84000);
        cudaFuncSetAttribute((const void*)pair_kernel<1,256>, cudaFuncAttributeMaxDynamicSharedMemorySize, 84000);
        cudaFuncSetAttribute((const void*)pair_kernel<2,256>, cudaFuncAttributeMaxDynamicSharedMemorySize, 84000);
        cudaFuncSetAttribute((const void*)fps_kernel, cudaFuncAttributeMaxDynamicSharedMemorySize, 66000);
    }

    float *gtfps, *f1, *g1, *f2, *g2, *e1r, *e2r, *d1c, *d2c, *d1f, *d2f;
    cudaGetSymbolAddress((void**)&gtfps, g_gtfps);
    cudaGetSymbolAddress((void**)&f1, g_f1);
    cudaGetSymbolAddress((void**)&g1, g_g1);
    cudaGetSymbolAddress((void**)&f2, g_f2);
    cudaGetSymbolAddress((void**)&g2, g_g2);
    cudaGetSymbolAddress((void**)&e1r, g_emd1r);
    cudaGetSymbolAddress((void**)&e2r, g_emd2r);
    cudaGetSymbolAddress((void**)&d1c, g_d1c);
    cudaGetSymbolAddress((void**)&d2c, g_d2c);
    cudaGetSymbolAddress((void**)&d1f, g_d1f);
    cudaGetSymbolAddress((void**)&d2f, g_d2f);

    // ---- fork: FPS + EMD1 on s1 ----
    cudaEventRecord(evFork, 0);
    cudaStreamWaitEvent(s1, evFork, 0);
    fps_kernel<<<2, FPS_T, 66000, s1>>>(gt);

    cudaMemcpyAsync(out,        coarse, 2 * 512 * 3 * sizeof(float),  cudaMemcpyDeviceToDevice);
    cudaMemcpyAsync(out + 3072, fine,   2 * 4096 * 3 * sizeof(float), cudaMemcpyDeviceToDevice);

    const int GX4 = (4096 + 55) / 56;   // 74 -> grid (74,2) = 148 = 1 block/SM
    const int GX1 = 1024 / 16;          // 64 (NTT=256, 16 rows/block)
    const int GXC = 512 / 16;           // 32

    // ---- stream 0: EMD2 chain ----
    for (int it = 0; it < 4; it++) {
        pair_kernel<0,896><<<dim3(GX4, 2), 896, 4096 * 16>>>(
            fine, 4096, IDENT_MASK, 4096 * 3, gt, 4096, IDENT_MASK, 4096 * 3,
            it == 0 ? nullptr : g2, f2, EPSLOG4096, iters, it);
        pair_kernel<0,896><<<dim3(GX4, 2), 896, 4096 * 16>>>(
            gt, 4096, IDENT_MASK, 4096 * 3, fine, 4096, IDENT_MASK, 4096 * 3,
            f2, g2, EPSLOG4096, iters, it);
    }
    pair_kernel<1,896><<<dim3(GX4, 2), 896, 4096 * 20>>>(
        fine, 4096, IDENT_MASK, 4096 * 3, gt, 4096, IDENT_MASK, 4096 * 3,
        g2, e2r, 0.0f, nullptr, 0);

    // ---- stream 0: chamfers ----
    pair_kernel<2,896><<<dim3(GX4, 2), 896, 4096 * 16>>>(
        fine, 4096, IDENT_MASK, 4096 * 3, gt, 4096, IDENT_MASK, 4096 * 3,
        nullptr, d2f, 0.0f, nullptr, 0);
    pair_kernel<2,896><<<dim3(GX4, 2), 896, 4096 * 16>>>(
        gt, 4096, IDENT_MASK, 4096 * 3, fine, 4096, IDENT_MASK, 4096 * 3,
        nullptr, d1f, 0.0f, nullptr, 0);
    pair_kernel<2,896><<<dim3(GX4, 2), 896, 512 * 16>>>(
        gt, 4096, IDENT_MASK, 4096 * 3, coarse, 512, IDENT_MASK, 512 * 3,
        nullptr, d1c, 0.0f, nullptr, 0);
    pair_kernel<2,256><<<dim3(GXC, 2), 256, 4096 * 16>>>(
        coarse, 512, IDENT_MASK, 512 * 3, gt, 4096, IDENT_MASK, 4096 * 3,
        nullptr, d2c, 0.0f, nullptr, 0);

    // ---- s1: EMD1 chain (after FPS) ----
    for (int it = 0; it < 4; it++) {
        pair_kernel<0,256><<<dim3(GX1, 2), 256, 1024 * 16, s1>>>(
            coarse, 1024, 511, 512 * 3, gtfps, 1024, IDENT_MASK, 1024 * 3,
            it == 0 ? nullptr : g1, f1, EPSLOG1024, iters, it);
        pair_kernel<0,256><<<dim3(GX1, 2), 256, 1024 * 16, s1>>>(
            gtfps, 1024, IDENT_MASK, 1024 * 3, coarse, 1024, 511, 512 * 3,
            f1, g1, EPSLOG1024, iters, it);
    }
    pair_kernel<1,256><<<dim3(GX1, 2), 256, 1024 * 20, s1>>>(
        coarse, 1024, 511, 512 * 3, gtfps, 1024, IDENT_MASK, 1024 * 3,
        g1, e1r, 0.0f, nullptr, 0);

    // ---- join, finalize ----
    cudaEventRecord(evJoin, s1);
    cudaStreamWaitEvent(0, evJoin, 0);
    finalize_kernel<<<2, 1024>>>(out);
}